// round 5
// baseline (speedup 1.0000x reference)
#include <cuda_runtime.h>
#include <math.h>

// Problem constants
#define B_  2
#define T_  2048
#define D_  2048
#define H_  16
#define HD_ 128

// ---------------- scratch (static device globals; no allocation) -------------
__device__ float g_q[(size_t)B_ * H_ * T_ * HD_];   // [b,h,t,hd]  tf32, rope applied
__device__ float g_k[(size_t)B_ * H_ * T_ * HD_];
__device__ float g_v[(size_t)B_ * H_ * T_ * HD_];
__device__ float g_y[(size_t)B_ * T_ * D_];         // attention output [b,t,d] fp32
__device__ float g_xp[(size_t)B_ * T_ * D_];        // x, tf32, k-permuted A layout
__device__ float g_yp[(size_t)B_ * T_ * D_];        // y, tf32, k-permuted A layout
__device__ float g_wqkvp[(size_t)D_ * 3 * HD_ * H_];// w_qkv tf32
__device__ float g_woutp[(size_t)D_ * D_];          // w_out tf32
__device__ float2 g_rope_tab[T_ * 64];              // (cos, sin)

// ============================================================================
// tf32 mma helpers
// ============================================================================
__device__ __forceinline__ unsigned f2tf32(float x) {
    unsigned r;
    asm("cvt.rna.tf32.f32 %0, %1;" : "=r"(r) : "f"(x));
    return r;
}
__device__ __forceinline__ float f2tf32f(float x) { return __uint_as_float(f2tf32(x)); }

__device__ __forceinline__ void mma_tf32(float c[4],
                                         unsigned a0, unsigned a1, unsigned a2, unsigned a3,
                                         unsigned b0, unsigned b1) {
    asm volatile(
        "mma.sync.aligned.m16n8k8.row.col.f32.tf32.tf32.f32 "
        "{%0,%1,%2,%3}, {%4,%5,%6,%7}, {%8,%9}, {%0,%1,%2,%3};"
        : "+f"(c[0]), "+f"(c[1]), "+f"(c[2]), "+f"(c[3])
        : "r"(a0), "r"(a1), "r"(a2), "r"(a3), "r"(b0), "r"(b1));
}

// cp.async helpers
__device__ __forceinline__ void cpa16(const void* dst, const void* src) {
    unsigned s = (unsigned)__cvta_generic_to_shared(dst);
    asm volatile("cp.async.cg.shared.global [%0], [%1], 16;" :: "r"(s), "l"(src));
}
__device__ __forceinline__ void cpa_commit() { asm volatile("cp.async.commit_group;"); }
template<int N> __device__ __forceinline__ void cpa_wait() {
    asm volatile("cp.async.wait_group %0;" :: "n"(N));
}

// Smem layout constants (projection GEMM)
#define A_STRIDE 36    // 32 permuted k-slots + pad, conflict-free LDS.128
#define B_STRIDE 132   // 128 n + pad, conflict-free
#define GEMM_SMEM_BYTES ((2*128*A_STRIDE + 2*32*B_STRIDE) * 4)

// ============================================================================
// one-shot prep kernels
// ============================================================================
__global__ void rope_tab_kernel()
{
    int idx = blockIdx.x * blockDim.x + threadIdx.x;
    if (idx >= T_ * 64) return;
    int t = idx >> 6, i = idx & 63;
    float inv = powf(10000.0f, -((float)(2 * i)) * (1.0f / 128.0f));
    float ang = (float)t * inv;
    float s, c;
    sincosf(ang, &s, &c);
    g_rope_tab[idx] = make_float2(c, s);
}

__global__ void conv_wqkv_kernel(const float4* __restrict__ in)
{
    int i = blockIdx.x * blockDim.x + threadIdx.x;
    if (i >= (D_ * 3 * HD_ * H_) / 4) return;
    float4 v = in[i];
    v.x = f2tf32f(v.x); v.y = f2tf32f(v.y); v.z = f2tf32f(v.z); v.w = f2tf32f(v.w);
    ((float4*)g_wqkvp)[i] = v;
}

__global__ void conv_wout_kernel(const float4* __restrict__ in)
{
    int i = blockIdx.x * blockDim.x + threadIdx.x;
    if (i >= (D_ * D_) / 4) return;
    float4 v = in[i];
    v.x = f2tf32f(v.x); v.y = f2tf32f(v.y); v.z = f2tf32f(v.z); v.w = f2tf32f(v.w);
    ((float4*)g_woutp)[i] = v;
}

// permute+convert: out[row][kb*32 + slot(kk)], slot(kk) = (kk&3)*8 + (kk>>2)
__device__ __forceinline__ void perm_store(float* dst, int idx, float4 v)
{
    int row = idx >> 9;            // 512 float4 per row of 2048
    int j = idx & 511;
    int kb = j >> 3;               // k-block
    int e = j & 7;                 // (k&31)>>2
    float* o = dst + (size_t)row * D_ + kb * 32 + e;
    o[0]  = f2tf32f(v.x);
    o[8]  = f2tf32f(v.y);
    o[16] = f2tf32f(v.z);
    o[24] = f2tf32f(v.w);
}

__global__ void perm_x_kernel(const float4* __restrict__ in)
{
    int i = blockIdx.x * blockDim.x + threadIdx.x;
    if (i >= (B_ * T_ * D_) / 4) return;
    perm_store(g_xp, i, in[i]);
}

__global__ void perm_y_kernel()
{
    int i = blockIdx.x * blockDim.x + threadIdx.x;
    if (i >= (B_ * T_ * D_) / 4) return;
    perm_store(g_yp, i, ((const float4*)g_y)[i]);
}

// ============================================================================
// epilogues
// ============================================================================
struct GemmCtx {
    int m0, n0, lane, warp_m, warp_n;
};

__device__ __forceinline__ void qkv_scatter_pair(int row, int col, float v0, float v1)
{
    int b = row >> 11, t = row & (T_ - 1);
    int h = col / (3 * HD_);
    int r = col % (3 * HD_);                  // even
    size_t base = (((size_t)(b * H_ + h)) * T_ + t) * HD_;
    if (r < 2 * HD_) {
        float* dst = (r < HD_) ? g_q : g_k;
        int rr = r & (HD_ - 1);
        float2 cs = g_rope_tab[(t << 6) + (rr >> 1)];
        float o0 = v0 * cs.x - v1 * cs.y;
        float o1 = v0 * cs.y + v1 * cs.x;
        dst[base + rr]     = f2tf32f(o0);
        dst[base + rr + 1] = f2tf32f(o1);
    } else {
        g_v[base + r - 2 * HD_]     = f2tf32f(v0);
        g_v[base + r - 2 * HD_ + 1] = f2tf32f(v1);
    }
}

struct QkvEpi {
    __device__ __forceinline__ void operator()(const GemmCtx& c, float acc[4][4][4]) const {
#pragma unroll
        for (int mt = 0; mt < 4; mt++) {
            int row = c.m0 + c.warp_m * 64 + mt * 16 + (c.lane >> 2);
#pragma unroll
            for (int nt = 0; nt < 4; nt++) {
                int col = c.n0 + c.warp_n * 32 + nt * 8 + (c.lane & 3) * 2;
                qkv_scatter_pair(row,     col, acc[mt][nt][0], acc[mt][nt][1]);
                qkv_scatter_pair(row + 8, col, acc[mt][nt][2], acc[mt][nt][3]);
            }
        }
    }
};

struct OutEpi {
    float* C;
    __device__ __forceinline__ void operator()(const GemmCtx& c, float acc[4][4][4]) const {
#pragma unroll
        for (int mt = 0; mt < 4; mt++) {
            int row = c.m0 + c.warp_m * 64 + mt * 16 + (c.lane >> 2);
#pragma unroll
            for (int nt = 0; nt < 4; nt++) {
                int col = c.n0 + c.warp_n * 32 + nt * 8 + (c.lane & 3) * 2;
                *(float2*)(C + (size_t)row * D_ + col) =
                    make_float2(acc[mt][nt][0], acc[mt][nt][1]);
                *(float2*)(C + (size_t)(row + 8) * D_ + col) =
                    make_float2(acc[mt][nt][2], acc[mt][nt][3]);
            }
        }
    }
};

// ============================================================================
// tf32 GEMM 128x128x32, 8 warps (2m x 4n), cp.async 2-stage double buffer.
// Ap: tf32, k-permuted layout [m][K]; Bt: tf32 row-major [K][N].
// ============================================================================
template <typename Epi>
__device__ __forceinline__ void gemm_tf32_body(const float* __restrict__ Ap,
                                               const float* __restrict__ Bt,
                                               int Kd, int Nd, Epi epi)
{
    extern __shared__ unsigned smg[];
    unsigned* As = smg;                       // [2][128*A_STRIDE]
    unsigned* Bs = smg + 2 * 128 * A_STRIDE;  // [2][32*B_STRIDE]

    const int tid = threadIdx.x;
    const int lane = tid & 31;
    const int warp = tid >> 5;
    const int warp_m = warp & 1;
    const int warp_n = warp >> 1;
    const int m0 = blockIdx.y * 128;
    const int n0 = blockIdx.x * 128;

    float acc[4][4][4];
#pragma unroll
    for (int mt = 0; mt < 4; mt++)
#pragma unroll
        for (int nt = 0; nt < 4; nt++)
#pragma unroll
            for (int e = 0; e < 4; e++) acc[mt][nt][e] = 0.f;

    // per-thread cp.async coordinates (4 chunks A, 4 chunks B)
    const int ar[4] = { tid >> 3 | 0, (tid + 256) >> 3, (tid + 512) >> 3, (tid + 768) >> 3 };
    const int ac = (tid & 7) << 2;
    const int bc = (tid & 31) << 2;

#define LOAD_TILE(k0, buf)                                                        \
    {                                                                             \
        _Pragma("unroll")                                                         \
        for (int i = 0; i < 4; i++) {                                             \
            int l = tid + 256 * i;                                                \
            int arow = l >> 3;                                                    \
            cpa16(&As[(buf) * 128 * A_STRIDE + arow * A_STRIDE + ac],             \
                  Ap + (size_t)(m0 + arow) * Kd + (k0) + ac);                     \
            int brow = l >> 5;                                                    \
            cpa16(&Bs[(buf) * 32 * B_STRIDE + brow * B_STRIDE + bc],              \
                  Bt + (size_t)((k0) + brow) * Nd + n0 + bc);                     \
        }                                                                         \
        cpa_commit();                                                             \
    }

    const int ntiles = Kd / 32;
    LOAD_TILE(0, 0);

    for (int it = 0; it < ntiles; it++) {
        if (it + 1 < ntiles) {
            LOAD_TILE((it + 1) * 32, (it + 1) & 1);
            cpa_wait<1>();
        } else {
            cpa_wait<0>();
        }
        __syncthreads();

        const unsigned* Ab = As + (it & 1) * 128 * A_STRIDE;
        const unsigned* Bb = Bs + (it & 1) * 32 * B_STRIDE;

#pragma unroll
        for (int h = 0; h < 2; h++) {
            uint4 alo[4], ahi[4];
#pragma unroll
            for (int mt = 0; mt < 4; mt++) {
                int r0 = warp_m * 64 + mt * 16 + (lane >> 2);
                int cbase = (lane & 3) * 8 + h * 4;
                alo[mt] = *(const uint4*)&Ab[r0 * A_STRIDE + cbase];
                ahi[mt] = *(const uint4*)&Ab[(r0 + 8) * A_STRIDE + cbase];
            }
#pragma unroll
            for (int sh = 0; sh < 2; sh++) {
                int s = 2 * h + sh;
                unsigned b0[4], b1[4];
#pragma unroll
                for (int nt = 0; nt < 4; nt++) {
                    int col = warp_n * 32 + nt * 8 + (lane >> 2);
                    b0[nt] = Bb[(8 * s + (lane & 3)) * B_STRIDE + col];
                    b1[nt] = Bb[(8 * s + 4 + (lane & 3)) * B_STRIDE + col];
                }
#pragma unroll
                for (int mt = 0; mt < 4; mt++) {
                    unsigned a0 = sh ? alo[mt].z : alo[mt].x;
                    unsigned a1 = sh ? ahi[mt].z : ahi[mt].x;
                    unsigned a2 = sh ? alo[mt].w : alo[mt].y;
                    unsigned a3 = sh ? ahi[mt].w : ahi[mt].y;
#pragma unroll
                    for (int nt = 0; nt < 4; nt++)
                        mma_tf32(acc[mt][nt], a0, a1, a2, a3, b0[nt], b1[nt]);
                }
            }
        }
        __syncthreads();   // all reads of buf (it&1) done before it's overwritten
    }
#undef LOAD_TILE
    (void)ar;

    GemmCtx ctx{m0, n0, lane, warp_m, warp_n};
    epi(ctx, acc);
}

__global__ __launch_bounds__(256, 1) void gemm_qkv_kernel()
{
    gemm_tf32_body(g_xp, g_wqkvp, D_, 3 * HD_ * H_, QkvEpi{});
}

__global__ __launch_bounds__(256, 1) void gemm_out_kernel(float* __restrict__ C)
{
    gemm_tf32_body(g_yp, g_woutp, D_, D_, OutEpi{C});
}

// ============================================================================
// Flash attention on tensor cores (tf32 mma.m16n8k8). (unchanged from round 4)
// BM=128, BN=64, HD=128. 256 threads = 8 warps.
// ============================================================================
#define KV_STR 132
#define PS_STR 68
#define ATTN_SMEM_BYTES ((4*64*KV_STR + 128*PS_STR) * 4)

__device__ __forceinline__ void load_kv_tile(float* Kbuf, float* Vbuf,
                                             const float* Kh, const float* Vh,
                                             int k0, int tid)
{
#pragma unroll
    for (int i = 0; i < 8; i++) {
        int idx = tid + i * 256;
        int row = idx >> 5, c16 = idx & 31;
        cpa16(Kbuf + row * KV_STR + c16 * 4, Kh + (size_t)(k0 + row) * HD_ + c16 * 4);
    }
#pragma unroll
    for (int i = 0; i < 8; i++) {
        int idx = tid + i * 256;
        int row = idx >> 5, c16 = idx & 31;
        cpa16(Vbuf + row * KV_STR + c16 * 4, Vh + (size_t)(k0 + row) * HD_ + c16 * 4);
    }
    cpa_commit();
}

__global__ __launch_bounds__(256, 1) void attn_kernel()
{
    extern __shared__ float sm[];
    float* Ks = sm;
    float* Vs = sm + 2 * 64 * KV_STR;
    float* Ps = sm + 4 * 64 * KV_STR;

    const int b = blockIdx.z, h = blockIdx.y;
    const int q0 = blockIdx.x * 128;
    const float* Qh = g_q + (((size_t)(b * H_ + h)) * T_) * HD_;
    const float* Kh = g_k + (((size_t)(b * H_ + h)) * T_) * HD_;
    const float* Vh = g_v + (((size_t)(b * H_ + h)) * T_) * HD_;

    const int tid = threadIdx.x;
    const int lane = tid & 31;
    const int w = tid >> 5;
    const int r1 = lane >> 2;
    const int cc = lane & 3;
    const int qrow1 = q0 + w * 16 + r1;
    const int qrow2 = qrow1 + 8;
    const int ntile = (q0 >> 6) + 2;

    load_kv_tile(Ks, Vs, Kh, Vh, 0, tid);

    unsigned qf[16][4];
#pragma unroll
    for (int s = 0; s < 16; s++) {
        qf[s][0] = __float_as_uint(Qh[(size_t)qrow1 * HD_ + 8 * s + cc]);
        qf[s][1] = __float_as_uint(Qh[(size_t)qrow2 * HD_ + 8 * s + cc]);
        qf[s][2] = __float_as_uint(Qh[(size_t)qrow1 * HD_ + 8 * s + 4 + cc]);
        qf[s][3] = __float_as_uint(Qh[(size_t)qrow2 * HD_ + 8 * s + 4 + cc]);
    }

    float oacc[16][4];
#pragma unroll
    for (int n = 0; n < 16; n++)
#pragma unroll
        for (int e = 0; e < 4; e++) oacc[n][e] = 0.f;
    float m1 = -1e30f, m2 = -1e30f, l1 = 0.f, l2 = 0.f;
    const float sm_scale = 0.08838834764831845f;

    for (int t = 0; t < ntile; t++) {
        const int k0 = t * 64;
        float* Kb = Ks + (t & 1) * 64 * KV_STR;
        float* Vb = Vs + (t & 1) * 64 * KV_STR;

        if (t + 1 < ntile) {
            load_kv_tile(Ks + ((t + 1) & 1) * 64 * KV_STR,
                         Vs + ((t + 1) & 1) * 64 * KV_STR,
                         Kh, Vh, k0 + 64, tid);
            cpa_wait<1>();
        } else {
            cpa_wait<0>();
        }
        __syncthreads();

        float sacc[8][4];
#pragma unroll
        for (int n = 0; n < 8; n++)
#pragma unroll
            for (int e = 0; e < 4; e++) sacc[n][e] = 0.f;

#pragma unroll
        for (int s = 0; s < 16; s++) {
#pragma unroll
            for (int n = 0; n < 8; n++) {
                unsigned b0 = __float_as_uint(Kb[(8 * n + r1) * KV_STR + 8 * s + cc]);
                unsigned b1 = __float_as_uint(Kb[(8 * n + r1) * KV_STR + 8 * s + 4 + cc]);
                mma_tf32(sacc[n], qf[s][0], qf[s][1], qf[s][2], qf[s][3], b0, b1);
            }
        }

        const bool need_mask = (t >= ntile - 2);
        float mx1 = -1e30f, mx2 = -1e30f;
#pragma unroll
        for (int n = 0; n < 8; n++) {
            int col = k0 + 8 * n + 2 * cc;
            float s0 = sacc[n][0] * sm_scale;
            float s1 = sacc[n][1] * sm_scale;
            float s2 = sacc[n][2] * sm_scale;
            float s3 = sacc[n][3] * sm_scale;
            if (need_mask) {
                if (col     > qrow1) s0 = -1e30f;
                if (col + 1 > qrow1) s1 = -1e30f;
                if (col     > qrow2) s2 = -1e30f;
                if (col + 1 > qrow2) s3 = -1e30f;
            }
            sacc[n][0] = s0; sacc[n][1] = s1; sacc[n][2] = s2; sacc[n][3] = s3;
            mx1 = fmaxf(mx1, fmaxf(s0, s1));
            mx2 = fmaxf(mx2, fmaxf(s2, s3));
        }
        mx1 = fmaxf(mx1, __shfl_xor_sync(0xffffffffu, mx1, 1));
        mx1 = fmaxf(mx1, __shfl_xor_sync(0xffffffffu, mx1, 2));
        mx2 = fmaxf(mx2, __shfl_xor_sync(0xffffffffu, mx2, 1));
        mx2 = fmaxf(mx2, __shfl_xor_sync(0xffffffffu, mx2, 2));
        float mn1 = fmaxf(m1, mx1), mn2 = fmaxf(m2, mx2);

        float sum1 = 0.f, sum2 = 0.f;
#pragma unroll
        for (int n = 0; n < 8; n++) {
            float p0 = __uint_as_float(f2tf32(__expf(sacc[n][0] - mn1)));
            float p1 = __uint_as_float(f2tf32(__expf(sacc[n][1] - mn1)));
            float p2 = __uint_as_float(f2tf32(__expf(sacc[n][2] - mn2)));
            float p3 = __uint_as_float(f2tf32(__expf(sacc[n][3] - mn2)));
            sum1 += p0 + p1;
            sum2 += p2 + p3;
            *(float2*)&Ps[(w * 16 + r1) * PS_STR + 8 * n + 2 * cc]     = make_float2(p0, p1);
            *(float2*)&Ps[(w * 16 + r1 + 8) * PS_STR + 8 * n + 2 * cc] = make_float2(p2, p3);
        }
        sum1 += __shfl_xor_sync(0xffffffffu, sum1, 1);
        sum1 += __shfl_xor_sync(0xffffffffu, sum1, 2);
        sum2 += __shfl_xor_sync(0xffffffffu, sum2, 1);
        sum2 += __shfl_xor_sync(0xffffffffu, sum2, 2);

        float sc1 = __expf(m1 - mn1), sc2 = __expf(m2 - mn2);
        l1 = l1 * sc1 + sum1;
        l2 = l2 * sc2 + sum2;
        m1 = mn1; m2 = mn2;
#pragma unroll
        for (int n = 0; n < 16; n++) {
            oacc[n][0] *= sc1; oacc[n][1] *= sc1;
            oacc[n][2] *= sc2; oacc[n][3] *= sc2;
        }
        __syncwarp();

#pragma unroll
        for (int s = 0; s < 8; s++) {
            unsigned a0 = __float_as_uint(Ps[(w * 16 + r1) * PS_STR + 8 * s + cc]);
            unsigned a1 = __float_as_uint(Ps[(w * 16 + r1 + 8) * PS_STR + 8 * s + cc]);
            unsigned a2 = __float_as_uint(Ps[(w * 16 + r1) * PS_STR + 8 * s + 4 + cc]);
            unsigned a3 = __float_as_uint(Ps[(w * 16 + r1 + 8) * PS_STR + 8 * s + 4 + cc]);
#pragma unroll
            for (int n = 0; n < 16; n++) {
                unsigned b0 = __float_as_uint(Vb[(8 * s + cc) * KV_STR + 8 * n + r1]);
                unsigned b1 = __float_as_uint(Vb[(8 * s + 4 + cc) * KV_STR + 8 * n + r1]);
                mma_tf32(oacc[n], a0, a1, a2, a3, b0, b1);
            }
        }
        __syncthreads();
    }

    float inv1 = 1.0f / l1, inv2 = 1.0f / l2;
    float* y1 = g_y + ((size_t)b * T_ + qrow1) * D_ + h * HD_;
    float* y2 = g_y + ((size_t)b * T_ + qrow2) * D_ + h * HD_;
#pragma unroll
    for (int n = 0; n < 16; n++) {
        int col = 8 * n + 2 * cc;
        *(float2*)(y1 + col) = make_float2(oacc[n][0] * inv1, oacc[n][1] * inv1);
        *(float2*)(y2 + col) = make_float2(oacc[n][2] * inv2, oacc[n][3] * inv2);
    }
}

// ============================================================================
extern "C" void kernel_launch(void* const* d_in, const int* in_sizes, int n_in,
                              void* d_out, int out_size)
{
    const float* x     = (const float*)d_in[0];
    const float* w_qkv = (const float*)d_in[1];
    const float* w_out = (const float*)d_in[2];
    float* out = (float*)d_out;

    cudaFuncSetAttribute(attn_kernel, cudaFuncAttributeMaxDynamicSharedMemorySize,
                         ATTN_SMEM_BYTES);
    cudaFuncSetAttribute(gemm_qkv_kernel, cudaFuncAttributeMaxDynamicSharedMemorySize,
                         GEMM_SMEM_BYTES);
    cudaFuncSetAttribute(gemm_out_kernel, cudaFuncAttributeMaxDynamicSharedMemorySize,
                         GEMM_SMEM_BYTES);

    // prep: rope table + tf32 conversions + x permute
    rope_tab_kernel<<<(T_ * 64 + 255) / 256, 256>>>();
    conv_wqkv_kernel<<<((D_ * 3 * HD_ * H_ / 4) + 255) / 256, 256>>>((const float4*)w_qkv);
    conv_wout_kernel<<<((D_ * D_ / 4) + 255) / 256, 256>>>((const float4*)w_out);
    perm_x_kernel<<<((B_ * T_ * D_ / 4) + 255) / 256, 256>>>((const float4*)x);

    dim3 g1(6144 / 128, (B_ * T_) / 128);
    gemm_qkv_kernel<<<g1, 256, GEMM_SMEM_BYTES>>>();

    dim3 g2(T_ / 128, H_, B_);
    attn_kernel<<<g2, 256, ATTN_SMEM_BYTES>>>();

    perm_y_kernel<<<((B_ * T_ * D_ / 4) + 255) / 256, 256>>>();

    dim3 g3(D_ / 128, (B_ * T_) / 128);
    gemm_out_kernel<<<g3, 256, GEMM_SMEM_BYTES>>>(out);
}

// round 6
// speedup vs baseline: 1.0179x; 1.0179x over previous
#include <cuda_runtime.h>
#include <math.h>

// Problem constants
#define B_  2
#define T_  2048
#define D_  2048
#define H_  16
#define HD_ 128

// ---------------- scratch (static device globals; no allocation) -------------
__device__ float g_q[(size_t)B_ * H_ * T_ * HD_];   // [b,h,t,hd] tf32, rope applied
__device__ float g_k[(size_t)B_ * H_ * T_ * HD_];
__device__ float g_v[(size_t)B_ * H_ * T_ * HD_];
__device__ float g_y[(size_t)B_ * T_ * D_];         // attention output [b,t,d]
__device__ float2 g_rope_tab[T_ * 64];              // (cos, sin)

// ============================================================================
// tf32 mma helpers
// ============================================================================
__device__ __forceinline__ unsigned f2tf32(float x) {
    unsigned r;
    asm("cvt.rna.tf32.f32 %0, %1;" : "=r"(r) : "f"(x));
    return r;
}
__device__ __forceinline__ float f2tf32f(float x) { return __uint_as_float(f2tf32(x)); }

__device__ __forceinline__ void mma_tf32(float c[4],
                                         unsigned a0, unsigned a1, unsigned a2, unsigned a3,
                                         unsigned b0, unsigned b1) {
    asm volatile(
        "mma.sync.aligned.m16n8k8.row.col.f32.tf32.tf32.f32 "
        "{%0,%1,%2,%3}, {%4,%5,%6,%7}, {%8,%9}, {%0,%1,%2,%3};"
        : "+f"(c[0]), "+f"(c[1]), "+f"(c[2]), "+f"(c[3])
        : "r"(a0), "r"(a1), "r"(a2), "r"(a3), "r"(b0), "r"(b1));
}

// cp.async helpers (attention only)
__device__ __forceinline__ void cpa16(const void* dst, const void* src) {
    unsigned s = (unsigned)__cvta_generic_to_shared(dst);
    asm volatile("cp.async.cg.shared.global [%0], [%1], 16;" :: "r"(s), "l"(src));
}
__device__ __forceinline__ void cpa_commit() { asm volatile("cp.async.commit_group;"); }
template<int N> __device__ __forceinline__ void cpa_wait() {
    asm volatile("cp.async.wait_group %0;" :: "n"(N));
}

// Smem layout constants (projection GEMM)
#define A_STRIDE 36    // 32 permuted k-slots + pad, conflict-free LDS.128
#define B_STRIDE 132   // 128 permuted n-slots + pad

// ============================================================================
// rope table
// ============================================================================
__global__ void rope_tab_kernel()
{
    int idx = blockIdx.x * blockDim.x + threadIdx.x;
    if (idx >= T_ * 64) return;
    int t = idx >> 6, i = idx & 63;
    float inv = powf(10000.0f, -((float)(2 * i)) * (1.0f / 128.0f));
    float ang = (float)t * inv;
    float s, c;
    sincosf(ang, &s, &c);
    g_rope_tab[idx] = make_float2(c, s);
}

// ============================================================================
// epilogues
// ============================================================================
struct GemmCtx {
    int m0, n0, lane, warp_m, warp_n;
};

__device__ __forceinline__ void qkv_scatter_pair(int row, int col, float v0, float v1)
{
    int b = row >> 11, t = row & (T_ - 1);
    int h = col / (3 * HD_);
    int r = col % (3 * HD_);                  // always even
    size_t base = (((size_t)(b * H_ + h)) * T_ + t) * HD_;
    if (r < 2 * HD_) {
        float* dst = (r < HD_) ? g_q : g_k;
        int rr = r & (HD_ - 1);
        float2 cs = g_rope_tab[(t << 6) + (rr >> 1)];
        float o0 = v0 * cs.x - v1 * cs.y;
        float o1 = v0 * cs.y + v1 * cs.x;
        dst[base + rr]     = f2tf32f(o0);
        dst[base + rr + 1] = f2tf32f(o1);
    } else {
        g_v[base + r - 2 * HD_]     = f2tf32f(v0);
        g_v[base + r - 2 * HD_ + 1] = f2tf32f(v1);
    }
}

struct QkvEpi {
    __device__ __forceinline__ void operator()(const GemmCtx& c, float acc[4][4][4]) const {
#pragma unroll
        for (int mt = 0; mt < 4; mt++) {
            int row = c.m0 + c.warp_m * 64 + mt * 16 + (c.lane >> 2);
#pragma unroll
            for (int nt = 0; nt < 4; nt++) {
                int col = c.n0 + c.warp_n * 32 + nt * 8 + (c.lane & 3) * 2;
                qkv_scatter_pair(row,     col, acc[mt][nt][0], acc[mt][nt][1]);
                qkv_scatter_pair(row + 8, col, acc[mt][nt][2], acc[mt][nt][3]);
            }
        }
    }
};

struct OutEpi {
    float* C;
    __device__ __forceinline__ void operator()(const GemmCtx& c, float acc[4][4][4]) const {
#pragma unroll
        for (int mt = 0; mt < 4; mt++) {
            int row = c.m0 + c.warp_m * 64 + mt * 16 + (c.lane >> 2);
#pragma unroll
            for (int nt = 0; nt < 4; nt++) {
                int col = c.n0 + c.warp_n * 32 + nt * 8 + (c.lane & 3) * 2;
                *(float2*)(C + (size_t)row * D_ + col) =
                    make_float2(acc[mt][nt][0], acc[mt][nt][1]);
                *(float2*)(C + (size_t)(row + 8) * D_ + col) =
                    make_float2(acc[mt][nt][2], acc[mt][nt][3]);
            }
        }
    }
};

// ============================================================================
// tf32 tensor-core GEMM 128x128x32, 256 threads (8 warps, 2m x 4n).
// Round-4 register-staged structure + permuted B smem so b-fragments are LDS.128.
// B smem slot for logical col c: (c&7)*16 + (c>>3).
// ============================================================================
template <typename Epi>
__device__ __forceinline__ void gemm_tf32_body(const float* __restrict__ A,
                                               const float* __restrict__ Bg,
                                               int Kd, int Nd, Epi epi)
{
    __shared__ unsigned As[128 * A_STRIDE];
    __shared__ unsigned Bs[32 * B_STRIDE];

    const int tid = threadIdx.x;
    const int lane = tid & 31;
    const int warp = tid >> 5;
    const int warp_m = warp & 1;
    const int warp_n = warp >> 1;
    const int m0 = blockIdx.y * 128;
    const int n0 = blockIdx.x * 128;

    float acc[4][4][4];
#pragma unroll
    for (int mt = 0; mt < 4; mt++)
#pragma unroll
        for (int nt = 0; nt < 4; nt++)
#pragma unroll
            for (int e = 0; e < 4; e++) acc[mt][nt][e] = 0.f;

    float4 aS[4], bS[4];
#pragma unroll
    for (int i = 0; i < 4; i++) {
        int l = tid + 256 * i;
        int ar = l >> 3, ac = (l & 7) << 2;
        aS[i] = *(const float4*)(A + (size_t)(m0 + ar) * Kd + ac);
        int kr = l >> 5, bc = (l & 31) << 2;
        bS[i] = *(const float4*)(Bg + (size_t)kr * Nd + n0 + bc);
    }

    for (int k0 = 0; k0 < Kd; k0 += 32) {
        // ---- STS with tf32 convert; A k-permuted, B n-permuted ----
#pragma unroll
        for (int i = 0; i < 4; i++) {
            int l = tid + 256 * i;
            int ar = l >> 3, ac = (l & 7) << 2;
            unsigned* dst = &As[ar * A_STRIDE];
            float va[4] = {aS[i].x, aS[i].y, aS[i].z, aS[i].w};
#pragma unroll
            for (int e = 0; e < 4; e++) {
                int k = ac + e;
                dst[(k & 3) * 8 + (k >> 2)] = f2tf32(va[e]);
            }
            int kr = l >> 5, bc = (l & 31) << 2;
            unsigned* bdst = &Bs[kr * B_STRIDE];
            float vb[4] = {bS[i].x, bS[i].y, bS[i].z, bS[i].w};
#pragma unroll
            for (int e = 0; e < 4; e++) {
                int c = bc + e;
                bdst[(c & 7) * 16 + (c >> 3)] = f2tf32(vb[e]);
            }
        }
        __syncthreads();

        // ---- prefetch next tile into regs ----
        if (k0 + 32 < Kd) {
#pragma unroll
            for (int i = 0; i < 4; i++) {
                int l = tid + 256 * i;
                int ar = l >> 3, ac = (l & 7) << 2;
                aS[i] = *(const float4*)(A + (size_t)(m0 + ar) * Kd + k0 + 32 + ac);
                int kr = l >> 5, bc = (l & 31) << 2;
                bS[i] = *(const float4*)(Bg + (size_t)(k0 + 32 + kr) * Nd + n0 + bc);
            }
        }

        // ---- compute: 4 k-steps (s), fragments via LDS.128 ----
#pragma unroll
        for (int h = 0; h < 2; h++) {
            uint4 alo[4], ahi[4];
#pragma unroll
            for (int mt = 0; mt < 4; mt++) {
                int r0 = warp_m * 64 + mt * 16 + (lane >> 2);
                int cbase = (lane & 3) * 8 + h * 4;
                alo[mt] = *(uint4*)&As[r0 * A_STRIDE + cbase];
                ahi[mt] = *(uint4*)&As[(r0 + 8) * A_STRIDE + cbase];
            }
#pragma unroll
            for (int sh = 0; sh < 2; sh++) {
                int s = 2 * h + sh;
                int bcol = (lane >> 2) * 16 + warp_n * 4;
                uint4 bl0 = *(uint4*)&Bs[(8 * s + (lane & 3)) * B_STRIDE + bcol];
                uint4 bl1 = *(uint4*)&Bs[(8 * s + 4 + (lane & 3)) * B_STRIDE + bcol];
                unsigned b0[4] = {bl0.x, bl0.y, bl0.z, bl0.w};
                unsigned b1[4] = {bl1.x, bl1.y, bl1.z, bl1.w};
#pragma unroll
                for (int mt = 0; mt < 4; mt++) {
                    unsigned a0 = sh ? alo[mt].z : alo[mt].x;
                    unsigned a1 = sh ? ahi[mt].z : ahi[mt].x;
                    unsigned a2 = sh ? alo[mt].w : alo[mt].y;
                    unsigned a3 = sh ? ahi[mt].w : ahi[mt].y;
#pragma unroll
                    for (int nt = 0; nt < 4; nt++)
                        mma_tf32(acc[mt][nt], a0, a1, a2, a3, b0[nt], b1[nt]);
                }
            }
        }
        __syncthreads();
    }

    GemmCtx ctx{m0, n0, lane, warp_m, warp_n};
    epi(ctx, acc);
}

__global__ __launch_bounds__(256, 1) void gemm_qkv_kernel(const float* __restrict__ A,
                                                          const float* __restrict__ W)
{
    gemm_tf32_body(A, W, D_, 3 * HD_ * H_, QkvEpi{});
}

__global__ __launch_bounds__(256, 1) void gemm_out_kernel(const float* __restrict__ W,
                                                          float* __restrict__ C)
{
    gemm_tf32_body(g_y, W, D_, D_, OutEpi{C});
}

// ============================================================================
// Flash attention on tensor cores (tf32 mma.m16n8k8). Unchanged from round 4.
// ============================================================================
#define KV_STR 132
#define PS_STR 68
#define ATTN_SMEM_BYTES ((4*64*KV_STR + 128*PS_STR) * 4)

__device__ __forceinline__ void load_kv_tile(float* Kbuf, float* Vbuf,
                                             const float* Kh, const float* Vh,
                                             int k0, int tid)
{
#pragma unroll
    for (int i = 0; i < 8; i++) {
        int idx = tid + i * 256;
        int row = idx >> 5, c16 = idx & 31;
        cpa16(Kbuf + row * KV_STR + c16 * 4, Kh + (size_t)(k0 + row) * HD_ + c16 * 4);
    }
#pragma unroll
    for (int i = 0; i < 8; i++) {
        int idx = tid + i * 256;
        int row = idx >> 5, c16 = idx & 31;
        cpa16(Vbuf + row * KV_STR + c16 * 4, Vh + (size_t)(k0 + row) * HD_ + c16 * 4);
    }
    cpa_commit();
}

__global__ __launch_bounds__(256, 1) void attn_kernel()
{
    extern __shared__ float sm[];
    float* Ks = sm;
    float* Vs = sm + 2 * 64 * KV_STR;
    float* Ps = sm + 4 * 64 * KV_STR;

    const int b = blockIdx.z, h = blockIdx.y;
    const int q0 = blockIdx.x * 128;
    const float* Qh = g_q + (((size_t)(b * H_ + h)) * T_) * HD_;
    const float* Kh = g_k + (((size_t)(b * H_ + h)) * T_) * HD_;
    const float* Vh = g_v + (((size_t)(b * H_ + h)) * T_) * HD_;

    const int tid = threadIdx.x;
    const int lane = tid & 31;
    const int w = tid >> 5;
    const int r1 = lane >> 2;
    const int cc = lane & 3;
    const int qrow1 = q0 + w * 16 + r1;
    const int qrow2 = qrow1 + 8;
    const int ntile = (q0 >> 6) + 2;

    load_kv_tile(Ks, Vs, Kh, Vh, 0, tid);

    unsigned qf[16][4];
#pragma unroll
    for (int s = 0; s < 16; s++) {
        qf[s][0] = __float_as_uint(Qh[(size_t)qrow1 * HD_ + 8 * s + cc]);
        qf[s][1] = __float_as_uint(Qh[(size_t)qrow2 * HD_ + 8 * s + cc]);
        qf[s][2] = __float_as_uint(Qh[(size_t)qrow1 * HD_ + 8 * s + 4 + cc]);
        qf[s][3] = __float_as_uint(Qh[(size_t)qrow2 * HD_ + 8 * s + 4 + cc]);
    }

    float oacc[16][4];
#pragma unroll
    for (int n = 0; n < 16; n++)
#pragma unroll
        for (int e = 0; e < 4; e++) oacc[n][e] = 0.f;
    float m1 = -1e30f, m2 = -1e30f, l1 = 0.f, l2 = 0.f;
    const float sm_scale = 0.08838834764831845f;

    for (int t = 0; t < ntile; t++) {
        const int k0 = t * 64;
        float* Kb = Ks + (t & 1) * 64 * KV_STR;
        float* Vb = Vs + (t & 1) * 64 * KV_STR;

        if (t + 1 < ntile) {
            load_kv_tile(Ks + ((t + 1) & 1) * 64 * KV_STR,
                         Vs + ((t + 1) & 1) * 64 * KV_STR,
                         Kh, Vh, k0 + 64, tid);
            cpa_wait<1>();
        } else {
            cpa_wait<0>();
        }
        __syncthreads();

        float sacc[8][4];
#pragma unroll
        for (int n = 0; n < 8; n++)
#pragma unroll
            for (int e = 0; e < 4; e++) sacc[n][e] = 0.f;

#pragma unroll
        for (int s = 0; s < 16; s++) {
#pragma unroll
            for (int n = 0; n < 8; n++) {
                unsigned b0 = __float_as_uint(Kb[(8 * n + r1) * KV_STR + 8 * s + cc]);
                unsigned b1 = __float_as_uint(Kb[(8 * n + r1) * KV_STR + 8 * s + 4 + cc]);
                mma_tf32(sacc[n], qf[s][0], qf[s][1], qf[s][2], qf[s][3], b0, b1);
            }
        }

        const bool need_mask = (t >= ntile - 2);
        float mx1 = -1e30f, mx2 = -1e30f;
#pragma unroll
        for (int n = 0; n < 8; n++) {
            int col = k0 + 8 * n + 2 * cc;
            float s0 = sacc[n][0] * sm_scale;
            float s1 = sacc[n][1] * sm_scale;
            float s2 = sacc[n][2] * sm_scale;
            float s3 = sacc[n][3] * sm_scale;
            if (need_mask) {
                if (col     > qrow1) s0 = -1e30f;
                if (col + 1 > qrow1) s1 = -1e30f;
                if (col     > qrow2) s2 = -1e30f;
                if (col + 1 > qrow2) s3 = -1e30f;
            }
            sacc[n][0] = s0; sacc[n][1] = s1; sacc[n][2] = s2; sacc[n][3] = s3;
            mx1 = fmaxf(mx1, fmaxf(s0, s1));
            mx2 = fmaxf(mx2, fmaxf(s2, s3));
        }
        mx1 = fmaxf(mx1, __shfl_xor_sync(0xffffffffu, mx1, 1));
        mx1 = fmaxf(mx1, __shfl_xor_sync(0xffffffffu, mx1, 2));
        mx2 = fmaxf(mx2, __shfl_xor_sync(0xffffffffu, mx2, 1));
        mx2 = fmaxf(mx2, __shfl_xor_sync(0xffffffffu, mx2, 2));
        float mn1 = fmaxf(m1, mx1), mn2 = fmaxf(m2, mx2);

        float sum1 = 0.f, sum2 = 0.f;
#pragma unroll
        for (int n = 0; n < 8; n++) {
            float p0 = __uint_as_float(f2tf32(__expf(sacc[n][0] - mn1)));
            float p1 = __uint_as_float(f2tf32(__expf(sacc[n][1] - mn1)));
            float p2 = __uint_as_float(f2tf32(__expf(sacc[n][2] - mn2)));
            float p3 = __uint_as_float(f2tf32(__expf(sacc[n][3] - mn2)));
            sum1 += p0 + p1;
            sum2 += p2 + p3;
            *(float2*)&Ps[(w * 16 + r1) * PS_STR + 8 * n + 2 * cc]     = make_float2(p0, p1);
            *(float2*)&Ps[(w * 16 + r1 + 8) * PS_STR + 8 * n + 2 * cc] = make_float2(p2, p3);
        }
        sum1 += __shfl_xor_sync(0xffffffffu, sum1, 1);
        sum1 += __shfl_xor_sync(0xffffffffu, sum1, 2);
        sum2 += __shfl_xor_sync(0xffffffffu, sum2, 1);
        sum2 += __shfl_xor_sync(0xffffffffu, sum2, 2);

        float sc1 = __expf(m1 - mn1), sc2 = __expf(m2 - mn2);
        l1 = l1 * sc1 + sum1;
        l2 = l2 * sc2 + sum2;
        m1 = mn1; m2 = mn2;
#pragma unroll
        for (int n = 0; n < 16; n++) {
            oacc[n][0] *= sc1; oacc[n][1] *= sc1;
            oacc[n][2] *= sc2; oacc[n][3] *= sc2;
        }
        __syncwarp();

#pragma unroll
        for (int s = 0; s < 8; s++) {
            unsigned a0 = __float_as_uint(Ps[(w * 16 + r1) * PS_STR + 8 * s + cc]);
            unsigned a1 = __float_as_uint(Ps[(w * 16 + r1 + 8) * PS_STR + 8 * s + cc]);
            unsigned a2 = __float_as_uint(Ps[(w * 16 + r1) * PS_STR + 8 * s + 4 + cc]);
            unsigned a3 = __float_as_uint(Ps[(w * 16 + r1 + 8) * PS_STR + 8 * s + 4 + cc]);
#pragma unroll
            for (int n = 0; n < 16; n++) {
                unsigned b0 = __float_as_uint(Vb[(8 * s + cc) * KV_STR + 8 * n + r1]);
                unsigned b1 = __float_as_uint(Vb[(8 * s + 4 + cc) * KV_STR + 8 * n + r1]);
                mma_tf32(oacc[n], a0, a1, a2, a3, b0, b1);
            }
        }
        __syncthreads();
    }

    float inv1 = 1.0f / l1, inv2 = 1.0f / l2;
    float* y1 = g_y + ((size_t)b * T_ + qrow1) * D_ + h * HD_;
    float* y2 = g_y + ((size_t)b * T_ + qrow2) * D_ + h * HD_;
#pragma unroll
    for (int n = 0; n < 16; n++) {
        int col = 8 * n + 2 * cc;
        *(float2*)(y1 + col) = make_float2(oacc[n][0] * inv1, oacc[n][1] * inv1);
        *(float2*)(y2 + col) = make_float2(oacc[n][2] * inv2, oacc[n][3] * inv2);
    }
}

// ============================================================================
extern "C" void kernel_launch(void* const* d_in, const int* in_sizes, int n_in,
                              void* d_out, int out_size)
{
    const float* x     = (const float*)d_in[0];
    const float* w_qkv = (const float*)d_in[1];
    const float* w_out = (const float*)d_in[2];
    float* out = (float*)d_out;

    cudaFuncSetAttribute(attn_kernel, cudaFuncAttributeMaxDynamicSharedMemorySize,
                         ATTN_SMEM_BYTES);

    rope_tab_kernel<<<(T_ * 64 + 255) / 256, 256>>>();

    dim3 g1(6144 / 128, (B_ * T_) / 128);
    gemm_qkv_kernel<<<g1, 256>>>(x, w_qkv);

    dim3 g2(T_ / 128, H_, B_);
    attn_kernel<<<g2, 256, ATTN_SMEM_BYTES>>>();

    dim3 g3(D_ / 128, (B_ * T_) / 128);
    gemm_out_kernel<<<g3, 256>>>(w_out, out);
}

// round 7
// speedup vs baseline: 1.0574x; 1.0388x over previous
#include <cuda_runtime.h>
#include <math.h>

// Problem constants
#define B_  2
#define T_  2048
#define D_  2048
#define H_  16
#define HD_ 128

// ---------------- scratch (static device globals; no allocation) -------------
__device__ float g_q[(size_t)B_ * H_ * T_ * HD_];   // [b,h,t,hd] tf32, rope applied
__device__ float g_k[(size_t)B_ * H_ * T_ * HD_];
__device__ float g_v[(size_t)B_ * H_ * T_ * HD_];
__device__ float g_y[(size_t)B_ * T_ * D_];         // attention output [b,t,d]
__device__ float2 g_rope_tab[T_ * 64];              // (cos, sin)

// ============================================================================
// tf32 mma helpers
// ============================================================================
__device__ __forceinline__ unsigned f2tf32(float x) {
    unsigned r;
    asm("cvt.rna.tf32.f32 %0, %1;" : "=r"(r) : "f"(x));
    return r;
}
__device__ __forceinline__ float f2tf32f(float x) { return __uint_as_float(f2tf32(x)); }

__device__ __forceinline__ void mma_tf32(float c[4],
                                         unsigned a0, unsigned a1, unsigned a2, unsigned a3,
                                         unsigned b0, unsigned b1) {
    asm volatile(
        "mma.sync.aligned.m16n8k8.row.col.f32.tf32.tf32.f32 "
        "{%0,%1,%2,%3}, {%4,%5,%6,%7}, {%8,%9}, {%0,%1,%2,%3};"
        : "+f"(c[0]), "+f"(c[1]), "+f"(c[2]), "+f"(c[3])
        : "r"(a0), "r"(a1), "r"(a2), "r"(a3), "r"(b0), "r"(b1));
}

// cp.async helpers (attention only)
__device__ __forceinline__ void cpa16(const void* dst, const void* src) {
    unsigned s = (unsigned)__cvta_generic_to_shared(dst);
    asm volatile("cp.async.cg.shared.global [%0], [%1], 16;" :: "r"(s), "l"(src));
}
__device__ __forceinline__ void cpa_commit() { asm volatile("cp.async.commit_group;"); }
template<int N> __device__ __forceinline__ void cpa_wait() {
    asm volatile("cp.async.wait_group %0;" :: "n"(N));
}

// Smem layout constants (projection GEMM) — round-4 layout, double-buffered
#define A_STRIDE 36    // 32 permuted k-slots + pad, conflict-free LDS.128
#define B_STRIDE 132   // 128 n + pad
#define GEMM_SMEM_BYTES ((2*128*A_STRIDE + 2*32*B_STRIDE) * 4)

// ============================================================================
// rope table
// ============================================================================
__global__ void rope_tab_kernel()
{
    int idx = blockIdx.x * blockDim.x + threadIdx.x;
    if (idx >= T_ * 64) return;
    int t = idx >> 6, i = idx & 63;
    float inv = powf(10000.0f, -((float)(2 * i)) * (1.0f / 128.0f));
    float ang = (float)t * inv;
    float s, c;
    sincosf(ang, &s, &c);
    g_rope_tab[idx] = make_float2(c, s);
}

// ============================================================================
// epilogues
// ============================================================================
struct GemmCtx {
    int m0, n0, lane, warp_m, warp_n;
};

__device__ __forceinline__ void qkv_scatter_pair(int row, int col, float v0, float v1)
{
    int b = row >> 11, t = row & (T_ - 1);
    int h = col / (3 * HD_);
    int r = col % (3 * HD_);                  // always even
    size_t base = (((size_t)(b * H_ + h)) * T_ + t) * HD_;
    if (r < 2 * HD_) {
        float* dst = (r < HD_) ? g_q : g_k;
        int rr = r & (HD_ - 1);
        float2 cs = g_rope_tab[(t << 6) + (rr >> 1)];
        float o0 = v0 * cs.x - v1 * cs.y;
        float o1 = v0 * cs.y + v1 * cs.x;
        dst[base + rr]     = f2tf32f(o0);
        dst[base + rr + 1] = f2tf32f(o1);
    } else {
        g_v[base + r - 2 * HD_]     = f2tf32f(v0);
        g_v[base + r - 2 * HD_ + 1] = f2tf32f(v1);
    }
}

struct QkvEpi {
    __device__ __forceinline__ void operator()(const GemmCtx& c, float acc[4][4][4]) const {
#pragma unroll
        for (int mt = 0; mt < 4; mt++) {
            int row = c.m0 + c.warp_m * 64 + mt * 16 + (c.lane >> 2);
#pragma unroll
            for (int nt = 0; nt < 4; nt++) {
                int col = c.n0 + c.warp_n * 32 + nt * 8 + (c.lane & 3) * 2;
                qkv_scatter_pair(row,     col, acc[mt][nt][0], acc[mt][nt][1]);
                qkv_scatter_pair(row + 8, col, acc[mt][nt][2], acc[mt][nt][3]);
            }
        }
    }
};

struct OutEpi {
    float* C;
    __device__ __forceinline__ void operator()(const GemmCtx& c, float acc[4][4][4]) const {
#pragma unroll
        for (int mt = 0; mt < 4; mt++) {
            int row = c.m0 + c.warp_m * 64 + mt * 16 + (c.lane >> 2);
#pragma unroll
            for (int nt = 0; nt < 4; nt++) {
                int col = c.n0 + c.warp_n * 32 + nt * 8 + (c.lane & 3) * 2;
                *(float2*)(C + (size_t)row * D_ + col) =
                    make_float2(acc[mt][nt][0], acc[mt][nt][1]);
                *(float2*)(C + (size_t)(row + 8) * D_ + col) =
                    make_float2(acc[mt][nt][2], acc[mt][nt][3]);
            }
        }
    }
};

// ============================================================================
// tf32 GEMM 128x128x32, 8 warps (2m x 4n), round-4 memory patterns,
// double-buffered smem: ONE __syncthreads per k-tile.
//   LDG regs(i+1) -> compute buf(i&1) -> STS(i+1)->buf((i+1)&1) -> sync
// ============================================================================
template <typename Epi>
__device__ __forceinline__ void gemm_tf32_body(const float* __restrict__ A,
                                               const float* __restrict__ Bg,
                                               int Kd, int Nd, Epi epi)
{
    extern __shared__ unsigned smg[];
    unsigned* As = smg;                       // [2][128*A_STRIDE]
    unsigned* Bs = smg + 2 * 128 * A_STRIDE;  // [2][32*B_STRIDE]

    const int tid = threadIdx.x;
    const int lane = tid & 31;
    const int warp = tid >> 5;
    const int warp_m = warp & 1;
    const int warp_n = warp >> 1;
    const int m0 = blockIdx.y * 128;
    const int n0 = blockIdx.x * 128;

    float acc[4][4][4];
#pragma unroll
    for (int mt = 0; mt < 4; mt++)
#pragma unroll
        for (int nt = 0; nt < 4; nt++)
#pragma unroll
            for (int e = 0; e < 4; e++) acc[mt][nt][e] = 0.f;

    float4 aS[4], bS[4];

#define LDG_TILE(k0)                                                            \
    {                                                                           \
        _Pragma("unroll")                                                       \
        for (int i = 0; i < 4; i++) {                                           \
            int l = tid + 256 * i;                                              \
            int ar = l >> 3, ac = (l & 7) << 2;                                 \
            aS[i] = *(const float4*)(A + (size_t)(m0 + ar) * Kd + (k0) + ac);   \
            int kr = l >> 5, bc = (l & 31) << 2;                                \
            bS[i] = *(const float4*)(Bg + (size_t)((k0) + kr) * Nd + n0 + bc);  \
        }                                                                       \
    }

#define STS_TILE(buf)                                                           \
    {                                                                           \
        unsigned* Ad = As + (buf) * 128 * A_STRIDE;                             \
        unsigned* Bd = Bs + (buf) * 32 * B_STRIDE;                              \
        _Pragma("unroll")                                                       \
        for (int i = 0; i < 4; i++) {                                           \
            int l = tid + 256 * i;                                              \
            int ar = l >> 3, ac = (l & 7) << 2;                                 \
            unsigned* dst = &Ad[ar * A_STRIDE];                                 \
            float va[4] = {aS[i].x, aS[i].y, aS[i].z, aS[i].w};                 \
            _Pragma("unroll")                                                   \
            for (int e = 0; e < 4; e++) {                                       \
                int k = ac + e;                                                 \
                dst[(k & 3) * 8 + (k >> 2)] = f2tf32(va[e]);                    \
            }                                                                   \
            int kr = l >> 5, bc = (l & 31) << 2;                                \
            uint4 bv;                                                           \
            bv.x = f2tf32(bS[i].x); bv.y = f2tf32(bS[i].y);                     \
            bv.z = f2tf32(bS[i].z); bv.w = f2tf32(bS[i].w);                     \
            *(uint4*)&Bd[kr * B_STRIDE + bc] = bv;                              \
        }                                                                       \
    }

    const int ntiles = Kd / 32;
    LDG_TILE(0);
    STS_TILE(0);
    __syncthreads();

    for (int it = 0; it < ntiles; it++) {
        const bool more = (it + 1 < ntiles);
        if (more) LDG_TILE((it + 1) * 32);

        const unsigned* Ab = As + (it & 1) * 128 * A_STRIDE;
        const unsigned* Bb = Bs + (it & 1) * 32 * B_STRIDE;

#pragma unroll
        for (int h = 0; h < 2; h++) {
            uint4 alo[4], ahi[4];
#pragma unroll
            for (int mt = 0; mt < 4; mt++) {
                int r0 = warp_m * 64 + mt * 16 + (lane >> 2);
                int cbase = (lane & 3) * 8 + h * 4;
                alo[mt] = *(const uint4*)&Ab[r0 * A_STRIDE + cbase];
                ahi[mt] = *(const uint4*)&Ab[(r0 + 8) * A_STRIDE + cbase];
            }
#pragma unroll
            for (int sh = 0; sh < 2; sh++) {
                int s = 2 * h + sh;
                unsigned b0[4], b1[4];
#pragma unroll
                for (int nt = 0; nt < 4; nt++) {
                    int col = warp_n * 32 + nt * 8 + (lane >> 2);
                    b0[nt] = Bb[(8 * s + (lane & 3)) * B_STRIDE + col];
                    b1[nt] = Bb[(8 * s + 4 + (lane & 3)) * B_STRIDE + col];
                }
#pragma unroll
                for (int mt = 0; mt < 4; mt++) {
                    unsigned a0 = sh ? alo[mt].z : alo[mt].x;
                    unsigned a1 = sh ? ahi[mt].z : ahi[mt].x;
                    unsigned a2 = sh ? alo[mt].w : alo[mt].y;
                    unsigned a3 = sh ? ahi[mt].w : ahi[mt].y;
#pragma unroll
                    for (int nt = 0; nt < 4; nt++)
                        mma_tf32(acc[mt][nt], a0, a1, a2, a3, b0[nt], b1[nt]);
                }
            }
        }

        if (more) STS_TILE((it + 1) & 1);   // writes buffer last read in iter it-1
        __syncthreads();
    }
#undef LDG_TILE
#undef STS_TILE

    GemmCtx ctx{m0, n0, lane, warp_m, warp_n};
    epi(ctx, acc);
}

__global__ __launch_bounds__(256, 1) void gemm_qkv_kernel(const float* __restrict__ A,
                                                          const float* __restrict__ W)
{
    gemm_tf32_body(A, W, D_, 3 * HD_ * H_, QkvEpi{});
}

__global__ __launch_bounds__(256, 1) void gemm_out_kernel(const float* __restrict__ W,
                                                          float* __restrict__ C)
{
    gemm_tf32_body(g_y, W, D_, D_, OutEpi{C});
}

// ============================================================================
// Flash attention on tensor cores (tf32 mma.m16n8k8). Unchanged from round 4.
// ============================================================================
#define KV_STR 132
#define PS_STR 68
#define ATTN_SMEM_BYTES ((4*64*KV_STR + 128*PS_STR) * 4)

__device__ __forceinline__ void load_kv_tile(float* Kbuf, float* Vbuf,
                                             const float* Kh, const float* Vh,
                                             int k0, int tid)
{
#pragma unroll
    for (int i = 0; i < 8; i++) {
        int idx = tid + i * 256;
        int row = idx >> 5, c16 = idx & 31;
        cpa16(Kbuf + row * KV_STR + c16 * 4, Kh + (size_t)(k0 + row) * HD_ + c16 * 4);
    }
#pragma unroll
    for (int i = 0; i < 8; i++) {
        int idx = tid + i * 256;
        int row = idx >> 5, c16 = idx & 31;
        cpa16(Vbuf + row * KV_STR + c16 * 4, Vh + (size_t)(k0 + row) * HD_ + c16 * 4);
    }
    cpa_commit();
}

__global__ __launch_bounds__(256, 1) void attn_kernel()
{
    extern __shared__ float sm[];
    float* Ks = sm;
    float* Vs = sm + 2 * 64 * KV_STR;
    float* Ps = sm + 4 * 64 * KV_STR;

    const int b = blockIdx.z, h = blockIdx.y;
    const int q0 = blockIdx.x * 128;
    const float* Qh = g_q + (((size_t)(b * H_ + h)) * T_) * HD_;
    const float* Kh = g_k + (((size_t)(b * H_ + h)) * T_) * HD_;
    const float* Vh = g_v + (((size_t)(b * H_ + h)) * T_) * HD_;

    const int tid = threadIdx.x;
    const int lane = tid & 31;
    const int w = tid >> 5;
    const int r1 = lane >> 2;
    const int cc = lane & 3;
    const int qrow1 = q0 + w * 16 + r1;
    const int qrow2 = qrow1 + 8;
    const int ntile = (q0 >> 6) + 2;

    load_kv_tile(Ks, Vs, Kh, Vh, 0, tid);

    unsigned qf[16][4];
#pragma unroll
    for (int s = 0; s < 16; s++) {
        qf[s][0] = __float_as_uint(Qh[(size_t)qrow1 * HD_ + 8 * s + cc]);
        qf[s][1] = __float_as_uint(Qh[(size_t)qrow2 * HD_ + 8 * s + cc]);
        qf[s][2] = __float_as_uint(Qh[(size_t)qrow1 * HD_ + 8 * s + 4 + cc]);
        qf[s][3] = __float_as_uint(Qh[(size_t)qrow2 * HD_ + 8 * s + 4 + cc]);
    }

    float oacc[16][4];
#pragma unroll
    for (int n = 0; n < 16; n++)
#pragma unroll
        for (int e = 0; e < 4; e++) oacc[n][e] = 0.f;
    float m1 = -1e30f, m2 = -1e30f, l1 = 0.f, l2 = 0.f;
    const float sm_scale = 0.08838834764831845f;

    for (int t = 0; t < ntile; t++) {
        const int k0 = t * 64;
        float* Kb = Ks + (t & 1) * 64 * KV_STR;
        float* Vb = Vs + (t & 1) * 64 * KV_STR;

        if (t + 1 < ntile) {
            load_kv_tile(Ks + ((t + 1) & 1) * 64 * KV_STR,
                         Vs + ((t + 1) & 1) * 64 * KV_STR,
                         Kh, Vh, k0 + 64, tid);
            cpa_wait<1>();
        } else {
            cpa_wait<0>();
        }
        __syncthreads();

        float sacc[8][4];
#pragma unroll
        for (int n = 0; n < 8; n++)
#pragma unroll
            for (int e = 0; e < 4; e++) sacc[n][e] = 0.f;

#pragma unroll
        for (int s = 0; s < 16; s++) {
#pragma unroll
            for (int n = 0; n < 8; n++) {
                unsigned b0 = __float_as_uint(Kb[(8 * n + r1) * KV_STR + 8 * s + cc]);
                unsigned b1 = __float_as_uint(Kb[(8 * n + r1) * KV_STR + 8 * s + 4 + cc]);
                mma_tf32(sacc[n], qf[s][0], qf[s][1], qf[s][2], qf[s][3], b0, b1);
            }
        }

        const bool need_mask = (t >= ntile - 2);
        float mx1 = -1e30f, mx2 = -1e30f;
#pragma unroll
        for (int n = 0; n < 8; n++) {
            int col = k0 + 8 * n + 2 * cc;
            float s0 = sacc[n][0] * sm_scale;
            float s1 = sacc[n][1] * sm_scale;
            float s2 = sacc[n][2] * sm_scale;
            float s3 = sacc[n][3] * sm_scale;
            if (need_mask) {
                if (col     > qrow1) s0 = -1e30f;
                if (col + 1 > qrow1) s1 = -1e30f;
                if (col     > qrow2) s2 = -1e30f;
                if (col + 1 > qrow2) s3 = -1e30f;
            }
            sacc[n][0] = s0; sacc[n][1] = s1; sacc[n][2] = s2; sacc[n][3] = s3;
            mx1 = fmaxf(mx1, fmaxf(s0, s1));
            mx2 = fmaxf(mx2, fmaxf(s2, s3));
        }
        mx1 = fmaxf(mx1, __shfl_xor_sync(0xffffffffu, mx1, 1));
        mx1 = fmaxf(mx1, __shfl_xor_sync(0xffffffffu, mx1, 2));
        mx2 = fmaxf(mx2, __shfl_xor_sync(0xffffffffu, mx2, 1));
        mx2 = fmaxf(mx2, __shfl_xor_sync(0xffffffffu, mx2, 2));
        float mn1 = fmaxf(m1, mx1), mn2 = fmaxf(m2, mx2);

        float sum1 = 0.f, sum2 = 0.f;
#pragma unroll
        for (int n = 0; n < 8; n++) {
            float p0 = __uint_as_float(f2tf32(__expf(sacc[n][0] - mn1)));
            float p1 = __uint_as_float(f2tf32(__expf(sacc[n][1] - mn1)));
            float p2 = __uint_as_float(f2tf32(__expf(sacc[n][2] - mn2)));
            float p3 = __uint_as_float(f2tf32(__expf(sacc[n][3] - mn2)));
            sum1 += p0 + p1;
            sum2 += p2 + p3;
            *(float2*)&Ps[(w * 16 + r1) * PS_STR + 8 * n + 2 * cc]     = make_float2(p0, p1);
            *(float2*)&Ps[(w * 16 + r1 + 8) * PS_STR + 8 * n + 2 * cc] = make_float2(p2, p3);
        }
        sum1 += __shfl_xor_sync(0xffffffffu, sum1, 1);
        sum1 += __shfl_xor_sync(0xffffffffu, sum1, 2);
        sum2 += __shfl_xor_sync(0xffffffffu, sum2, 1);
        sum2 += __shfl_xor_sync(0xffffffffu, sum2, 2);

        float sc1 = __expf(m1 - mn1), sc2 = __expf(m2 - mn2);
        l1 = l1 * sc1 + sum1;
        l2 = l2 * sc2 + sum2;
        m1 = mn1; m2 = mn2;
#pragma unroll
        for (int n = 0; n < 16; n++) {
            oacc[n][0] *= sc1; oacc[n][1] *= sc1;
            oacc[n][2] *= sc2; oacc[n][3] *= sc2;
        }
        __syncwarp();

#pragma unroll
        for (int s = 0; s < 8; s++) {
            unsigned a0 = __float_as_uint(Ps[(w * 16 + r1) * PS_STR + 8 * s + cc]);
            unsigned a1 = __float_as_uint(Ps[(w * 16 + r1 + 8) * PS_STR + 8 * s + cc]);
            unsigned a2 = __float_as_uint(Ps[(w * 16 + r1) * PS_STR + 8 * s + 4 + cc]);
            unsigned a3 = __float_as_uint(Ps[(w * 16 + r1 + 8) * PS_STR + 8 * s + 4 + cc]);
#pragma unroll
            for (int n = 0; n < 16; n++) {
                unsigned b0 = __float_as_uint(Vb[(8 * s + cc) * KV_STR + 8 * n + r1]);
                unsigned b1 = __float_as_uint(Vb[(8 * s + 4 + cc) * KV_STR + 8 * n + r1]);
                mma_tf32(oacc[n], a0, a1, a2, a3, b0, b1);
            }
        }
        __syncthreads();
    }

    float inv1 = 1.0f / l1, inv2 = 1.0f / l2;
    float* y1 = g_y + ((size_t)b * T_ + qrow1) * D_ + h * HD_;
    float* y2 = g_y + ((size_t)b * T_ + qrow2) * D_ + h * HD_;
#pragma unroll
    for (int n = 0; n < 16; n++) {
        int col = 8 * n + 2 * cc;
        *(float2*)(y1 + col) = make_float2(oacc[n][0] * inv1, oacc[n][1] * inv1);
        *(float2*)(y2 + col) = make_float2(oacc[n][2] * inv2, oacc[n][3] * inv2);
    }
}

// ============================================================================
extern "C" void kernel_launch(void* const* d_in, const int* in_sizes, int n_in,
                              void* d_out, int out_size)
{
    const float* x     = (const float*)d_in[0];
    const float* w_qkv = (const float*)d_in[1];
    const float* w_out = (const float*)d_in[2];
    float* out = (float*)d_out;

    cudaFuncSetAttribute(attn_kernel, cudaFuncAttributeMaxDynamicSharedMemorySize,
                         ATTN_SMEM_BYTES);
    cudaFuncSetAttribute(gemm_qkv_kernel, cudaFuncAttributeMaxDynamicSharedMemorySize,
                         GEMM_SMEM_BYTES);
    cudaFuncSetAttribute(gemm_out_kernel, cudaFuncAttributeMaxDynamicSharedMemorySize,
                         GEMM_SMEM_BYTES);

    rope_tab_kernel<<<(T_ * 64 + 255) / 256, 256>>>();

    dim3 g1(6144 / 128, (B_ * T_) / 128);
    gemm_qkv_kernel<<<g1, 256, GEMM_SMEM_BYTES>>>(x, w_qkv);

    dim3 g2(T_ / 128, H_, B_);
    attn_kernel<<<g2, 256, ATTN_SMEM_BYTES>>>();

    dim3 g3(D_ / 128, (B_ * T_) / 128);
    gemm_out_kernel<<<g3, 256, GEMM_SMEM_BYTES>>>(w_out, out);
}

// round 9
// speedup vs baseline: 1.9741x; 1.8668x over previous
#include <cuda_runtime.h>
#include <cuda_fp16.h>
#include <math.h>
#include <stdint.h>

// Problem constants
#define B_  2
#define T_  2048
#define D_  2048
#define H_  16
#define HD_ 128

// ---------------- scratch (static device globals; no allocation) -------------
__device__ __align__(16) __half g_q[(size_t)B_ * H_ * T_ * HD_];  // rope applied
__device__ __align__(16) __half g_k[(size_t)B_ * H_ * T_ * HD_];
__device__ __align__(16) __half g_v[(size_t)B_ * H_ * T_ * HD_];
__device__ __align__(16) __half g_y[(size_t)B_ * T_ * D_];        // attn output
__device__ float2 g_rope_tab[T_ * 64];                            // (cos, sin)

// ============================================================================
// helpers
// ============================================================================
__device__ __forceinline__ uint32_t h2_u32(__half2 h) {
    return *reinterpret_cast<uint32_t*>(&h);
}

__device__ __forceinline__ void mma_f16(float c[4],
                                        uint32_t a0, uint32_t a1, uint32_t a2, uint32_t a3,
                                        uint32_t b0, uint32_t b1) {
    asm volatile(
        "mma.sync.aligned.m16n8k16.row.col.f32.f16.f16.f32 "
        "{%0,%1,%2,%3}, {%4,%5,%6,%7}, {%8,%9}, {%0,%1,%2,%3};"
        : "+f"(c[0]), "+f"(c[1]), "+f"(c[2]), "+f"(c[3])
        : "r"(a0), "r"(a1), "r"(a2), "r"(a3), "r"(b0), "r"(b1));
}

__device__ __forceinline__ void ldsm_x4(uint32_t r[4], uint32_t addr) {
    asm volatile("ldmatrix.sync.aligned.m8n8.x4.shared.b16 {%0,%1,%2,%3}, [%4];"
                 : "=r"(r[0]), "=r"(r[1]), "=r"(r[2]), "=r"(r[3]) : "r"(addr));
}
__device__ __forceinline__ void ldsm_x4_t(uint32_t r[4], uint32_t addr) {
    asm volatile("ldmatrix.sync.aligned.m8n8.x4.trans.shared.b16 {%0,%1,%2,%3}, [%4];"
                 : "=r"(r[0]), "=r"(r[1]), "=r"(r[2]), "=r"(r[3]) : "r"(addr));
}

__device__ __forceinline__ void cpa16s(uint32_t saddr, const void* src) {
    asm volatile("cp.async.cg.shared.global [%0], [%1], 16;" :: "r"(saddr), "l"(src));
}
__device__ __forceinline__ void cpa_commit() { asm volatile("cp.async.commit_group;"); }
template<int N> __device__ __forceinline__ void cpa_wait() {
    asm volatile("cp.async.wait_group %0;" :: "n"(N));
}

__device__ __forceinline__ uint32_t smem_u32(const void* p) {
    uint32_t a;
    asm("{ .reg .u64 t; cvta.to.shared.u64 t, %1; cvt.u32.u64 %0, t; }" : "=r"(a) : "l"(p));
    return a;
}

// ============================================================================
// rope table
// ============================================================================
__global__ void rope_tab_kernel()
{
    int idx = blockIdx.x * blockDim.x + threadIdx.x;
    if (idx >= T_ * 64) return;
    int t = idx >> 6, i = idx & 63;
    float inv = powf(10000.0f, -((float)(2 * i)) * (1.0f / 128.0f));
    float ang = (float)t * inv;
    float s, c;
    sincosf(ang, &s, &c);
    g_rope_tab[idx] = make_float2(c, s);
}

// ============================================================================
// fp16 GEMM 128x128x(k-chunk 32), 256 threads (8 warps 2m x 4n).
// A smem [128][AROW] halves (row-major, pad 40); B smem [32][BROW] (pad 136).
// Fragments: A ldmatrix.x4, B ldmatrix.x4.trans. fp32 accumulate.
// ============================================================================
#define AROW 40
#define BROW 136

struct GemmCtx { int m0, n0, lane, warp_m, warp_n; };

struct AStageF {          // fp32 global source
    float4 v[4];
    __device__ __forceinline__ void ldg(const float* A, int m0, int Kd, int k0, int tid) {
#pragma unroll
        for (int i = 0; i < 4; i++) {
            int l = tid + 256 * i;
            v[i] = *(const float4*)(A + (size_t)(m0 + (l >> 3)) * Kd + k0 + (l & 7) * 4);
        }
    }
    __device__ __forceinline__ void sts(__half* As, int tid) {
#pragma unroll
        for (int i = 0; i < 4; i++) {
            int l = tid + 256 * i;
            __half2 h0 = __floats2half2_rn(v[i].x, v[i].y);
            __half2 h1 = __floats2half2_rn(v[i].z, v[i].w);
            uint2 u = make_uint2(h2_u32(h0), h2_u32(h1));
            *(uint2*)&As[(l >> 3) * AROW + (l & 7) * 4] = u;
        }
    }
};

struct AStageH {          // fp16 global source (g_y)
    uint2 v[4];
    __device__ __forceinline__ void ldg(const __half* A, int m0, int Kd, int k0, int tid) {
#pragma unroll
        for (int i = 0; i < 4; i++) {
            int l = tid + 256 * i;
            v[i] = *(const uint2*)(A + (size_t)(m0 + (l >> 3)) * Kd + k0 + (l & 7) * 4);
        }
    }
    __device__ __forceinline__ void sts(__half* As, int tid) {
#pragma unroll
        for (int i = 0; i < 4; i++) {
            int l = tid + 256 * i;
            *(uint2*)&As[(l >> 3) * AROW + (l & 7) * 4] = v[i];
        }
    }
};

template <typename T> struct AStageSel;
template <> struct AStageSel<float>  { using type = AStageF; };
template <> struct AStageSel<__half> { using type = AStageH; };

struct BStage {           // fp32 weights
    float4 v[4];
    __device__ __forceinline__ void ldg(const float* Bg, int n0, int Nd, int k0, int tid) {
#pragma unroll
        for (int i = 0; i < 4; i++) {
            int l = tid + 256 * i;
            v[i] = *(const float4*)(Bg + (size_t)(k0 + (l >> 5)) * Nd + n0 + (l & 31) * 4);
        }
    }
    __device__ __forceinline__ void sts(__half* Bs, int tid) {
#pragma unroll
        for (int i = 0; i < 4; i++) {
            int l = tid + 256 * i;
            __half2 h0 = __floats2half2_rn(v[i].x, v[i].y);
            __half2 h1 = __floats2half2_rn(v[i].z, v[i].w);
            uint2 u = make_uint2(h2_u32(h0), h2_u32(h1));
            *(uint2*)&Bs[(l >> 5) * BROW + (l & 31) * 4] = u;
        }
    }
};

template <typename AT, typename Epi>
__device__ __forceinline__ void gemm_f16_body(const AT* __restrict__ A,
                                              const float* __restrict__ Bg,
                                              int Kd, int Nd, Epi epi)
{
    __shared__ __half As[128 * AROW];
    __shared__ __half Bs[32 * BROW];

    const int tid = threadIdx.x;
    const int lane = tid & 31;
    const int warp = tid >> 5;
    const int warp_m = warp & 1;
    const int warp_n = warp >> 1;
    const int m0 = blockIdx.y * 128;
    const int n0 = blockIdx.x * 128;

    float acc[4][4][4];
#pragma unroll
    for (int mt = 0; mt < 4; mt++)
#pragma unroll
        for (int nt = 0; nt < 4; nt++)
#pragma unroll
            for (int e = 0; e < 4; e++) acc[mt][nt][e] = 0.f;

    // ldmatrix lane addresses (bytes)
    const uint32_t as_u = smem_u32(As);
    const uint32_t bs_u = smem_u32(Bs);
    // A x4: m0..m3 = (rows0-7,k0-7),(rows8-15,k0-7),(rows0-7,k8-15),(rows8-15,k8-15)
    const uint32_t a_lane = as_u +
        (uint32_t)((warp_m * 64 + (lane & 7) + ((lane >> 3) & 1) * 8) * AROW +
                   (lane >> 4) * 8) * 2;
    // B x4.trans on [k][n]: m0..m3 = (k0-7,n0-7),(k8-15,n0-7),(k0-7,n8-15),(k8-15,n8-15)
    const uint32_t b_lane = bs_u +
        (uint32_t)(((lane & 7) + ((lane >> 3) & 1) * 8) * BROW +
                   warp_n * 32 + (lane >> 4) * 8) * 2;

    typename AStageSel<AT>::type ast;
    BStage bst;
    ast.ldg(A, m0, Kd, 0, tid);
    bst.ldg(Bg, n0, Nd, 0, tid);

    for (int k0 = 0; k0 < Kd; k0 += 32) {
        ast.sts(As, tid);
        bst.sts(Bs, tid);
        __syncthreads();

        if (k0 + 32 < Kd) {
            ast.ldg(A, m0, Kd, k0 + 32, tid);
            bst.ldg(Bg, n0, Nd, k0 + 32, tid);
        }

#pragma unroll
        for (int s = 0; s < 2; s++) {
            uint32_t af[4][4];
#pragma unroll
            for (int mt = 0; mt < 4; mt++)
                ldsm_x4(af[mt], a_lane + (uint32_t)(mt * 16 * AROW * 2 + s * 32));
            uint32_t bf[2][4];
#pragma unroll
            for (int nt2 = 0; nt2 < 2; nt2++)
                ldsm_x4_t(bf[nt2], b_lane + (uint32_t)(s * 16 * BROW * 2 + nt2 * 32));
#pragma unroll
            for (int mt = 0; mt < 4; mt++)
#pragma unroll
                for (int nt = 0; nt < 4; nt++)
                    mma_f16(acc[mt][nt],
                            af[mt][0], af[mt][1], af[mt][2], af[mt][3],
                            bf[nt >> 1][(nt & 1) * 2], bf[nt >> 1][(nt & 1) * 2 + 1]);
        }
        __syncthreads();
    }

    GemmCtx ctx{m0, n0, lane, warp_m, warp_n};
    epi(ctx, acc);
}

// ---------------- epilogues --------------------------------------------------
__device__ __forceinline__ void qkv_scatter_pair(int row, int col, float v0, float v1)
{
    int b = row >> 11, t = row & (T_ - 1);
    int h = col / (3 * HD_);
    int r = col % (3 * HD_);                 // always even
    size_t base = (((size_t)(b * H_ + h)) * T_ + t) * HD_;
    if (r < 2 * HD_) {
        __half* dst = (r < HD_) ? g_q : g_k;
        int rr = r & (HD_ - 1);
        float2 cs = g_rope_tab[(t << 6) + (rr >> 1)];
        float o0 = v0 * cs.x - v1 * cs.y;
        float o1 = v0 * cs.y + v1 * cs.x;
        *(__half2*)&dst[base + rr] = __floats2half2_rn(o0, o1);
    } else {
        *(__half2*)&g_v[base + r - 2 * HD_] = __floats2half2_rn(v0, v1);
    }
}

struct QkvEpi {
    __device__ __forceinline__ void operator()(const GemmCtx& c, float acc[4][4][4]) const {
#pragma unroll
        for (int mt = 0; mt < 4; mt++) {
            int row = c.m0 + c.warp_m * 64 + mt * 16 + (c.lane >> 2);
#pragma unroll
            for (int nt = 0; nt < 4; nt++) {
                int col = c.n0 + c.warp_n * 32 + nt * 8 + (c.lane & 3) * 2;
                qkv_scatter_pair(row,     col, acc[mt][nt][0], acc[mt][nt][1]);
                qkv_scatter_pair(row + 8, col, acc[mt][nt][2], acc[mt][nt][3]);
            }
        }
    }
};

struct OutEpi {
    float* C;
    __device__ __forceinline__ void operator()(const GemmCtx& c, float acc[4][4][4]) const {
#pragma unroll
        for (int mt = 0; mt < 4; mt++) {
            int row = c.m0 + c.warp_m * 64 + mt * 16 + (c.lane >> 2);
#pragma unroll
            for (int nt = 0; nt < 4; nt++) {
                int col = c.n0 + c.warp_n * 32 + nt * 8 + (c.lane & 3) * 2;
                *(float2*)(C + (size_t)row * D_ + col) =
                    make_float2(acc[mt][nt][0], acc[mt][nt][1]);
                *(float2*)(C + (size_t)(row + 8) * D_ + col) =
                    make_float2(acc[mt][nt][2], acc[mt][nt][3]);
            }
        }
    }
};

__global__ __launch_bounds__(256, 1) void gemm_qkv_kernel(const float* __restrict__ A,
                                                          const float* __restrict__ W)
{
    gemm_f16_body<float>(A, W, D_, 3 * HD_ * H_, QkvEpi{});
}

__global__ __launch_bounds__(256, 1) void gemm_out_kernel(const float* __restrict__ W,
                                                          float* __restrict__ C)
{
    gemm_f16_body<__half>(g_y, W, D_, D_, OutEpi{C});
}

// ============================================================================
// Flash attention, fp16 mma.m16n8k16. BM=128, BN=64, HD=128; 8 warps.
// Q frags in regs; K/V fp16 smem double-buffered via cp.async;
// P stays in registers (accumulator layout == A-fragment layout).
// ============================================================================
#define KROWH 136
#define KV_TILE_BYTES (64 * KROWH * 2)          // 17408
#define ATTN_SMEM_BYTES (4 * KV_TILE_BYTES)     // 69632

__device__ __forceinline__ void load_kv(uint32_t sm_u, int buf,
                                        const __half* Kh, const __half* Vh,
                                        int k0, int tid)
{
    uint32_t kb = sm_u + buf * KV_TILE_BYTES;
    uint32_t vb = sm_u + 2 * KV_TILE_BYTES + buf * KV_TILE_BYTES;
#pragma unroll
    for (int i = 0; i < 4; i++) {
        int idx = tid + i * 256;
        int row = idx >> 4, c16 = idx & 15;
        cpa16s(kb + row * (KROWH * 2) + c16 * 16,
               Kh + (size_t)(k0 + row) * HD_ + c16 * 8);
    }
#pragma unroll
    for (int i = 0; i < 4; i++) {
        int idx = tid + i * 256;
        int row = idx >> 4, c16 = idx & 15;
        cpa16s(vb + row * (KROWH * 2) + c16 * 16,
               Vh + (size_t)(k0 + row) * HD_ + c16 * 8);
    }
    cpa_commit();
}

__global__ __launch_bounds__(256, 1) void attn_kernel()
{
    extern __shared__ __half smh[];
    const uint32_t sm_u = smem_u32(smh);

    const int b = blockIdx.z, h = blockIdx.y;
    const int q0 = blockIdx.x * 128;
    const __half* Qh = g_q + (((size_t)(b * H_ + h)) * T_) * HD_;
    const __half* Kh = g_k + (((size_t)(b * H_ + h)) * T_) * HD_;
    const __half* Vh = g_v + (((size_t)(b * H_ + h)) * T_) * HD_;

    const int tid = threadIdx.x;
    const int lane = tid & 31;
    const int w = tid >> 5;
    const int r1 = lane >> 2;
    const int cc = lane & 3;
    const int qrow1 = q0 + w * 16 + r1;
    const int qrow2 = qrow1 + 8;
    const int ntile = (q0 >> 6) + 2;

    load_kv(sm_u, 0, Kh, Vh, 0, tid);

    // Q fragments: 8 k16-steps over HD=128
    uint32_t qf[8][4];
#pragma unroll
    for (int s = 0; s < 8; s++) {
        qf[s][0] = *(const uint32_t*)(Qh + (size_t)qrow1 * HD_ + 16 * s + 2 * cc);
        qf[s][1] = *(const uint32_t*)(Qh + (size_t)qrow2 * HD_ + 16 * s + 2 * cc);
        qf[s][2] = *(const uint32_t*)(Qh + (size_t)qrow1 * HD_ + 16 * s + 8 + 2 * cc);
        qf[s][3] = *(const uint32_t*)(Qh + (size_t)qrow2 * HD_ + 16 * s + 8 + 2 * cc);
    }

    float oacc[16][4];
#pragma unroll
    for (int n = 0; n < 16; n++)
#pragma unroll
        for (int e = 0; e < 4; e++) oacc[n][e] = 0.f;
    float m1 = -1e30f, m2 = -1e30f, l1 = 0.f, l2 = 0.f;
    const float sm_scale = 0.08838834764831845f;   // 1/sqrt(128)

    // ldmatrix lane offsets (bytes)
    // K (non-trans, [key][hd]): m0..m3 = (keys0-7,hd0-7),(keys0-7,hd+8),(keys+8,hd0-7),(keys+8,hd+8)
    const uint32_t k_off =
        (uint32_t)(((lane & 7) + (lane >> 4) * 8) * KROWH + ((lane >> 3) & 1) * 8) * 2;
    // V (trans, [key][hd]): m0..m3 = (keys0-7,hd0-7),(keys+8,hd0-7),(keys0-7,hd+8),(keys+8,hd+8)
    const uint32_t v_off =
        (uint32_t)(((lane & 7) + ((lane >> 3) & 1) * 8) * KROWH + (lane >> 4) * 8) * 2;

    for (int t = 0; t < ntile; t++) {
        const int k0 = t * 64;
        const uint32_t Kb = sm_u + (t & 1) * KV_TILE_BYTES;
        const uint32_t Vb = sm_u + 2 * KV_TILE_BYTES + (t & 1) * KV_TILE_BYTES;

        if (t + 1 < ntile) {
            load_kv(sm_u, (t + 1) & 1, Kh, Vh, k0 + 64, tid);
            cpa_wait<1>();
        } else {
            cpa_wait<0>();
        }
        __syncthreads();

        // ---- S = Q K^T ----
        float sacc[8][4];
#pragma unroll
        for (int n = 0; n < 8; n++)
#pragma unroll
            for (int e = 0; e < 4; e++) sacc[n][e] = 0.f;

#pragma unroll
        for (int s = 0; s < 8; s++) {
#pragma unroll
            for (int j = 0; j < 4; j++) {
                uint32_t bb[4];
                ldsm_x4(bb, Kb + k_off + (uint32_t)(j * 16 * KROWH * 2 + s * 32));
                mma_f16(sacc[2 * j],     qf[s][0], qf[s][1], qf[s][2], qf[s][3], bb[0], bb[1]);
                mma_f16(sacc[2 * j + 1], qf[s][0], qf[s][1], qf[s][2], qf[s][3], bb[2], bb[3]);
            }
        }

        // ---- mask + online softmax ----
        const bool need_mask = (t >= ntile - 2);
        float mx1 = -1e30f, mx2 = -1e30f;
#pragma unroll
        for (int n = 0; n < 8; n++) {
            int col = k0 + 8 * n + 2 * cc;
            float s0 = sacc[n][0] * sm_scale;
            float s1 = sacc[n][1] * sm_scale;
            float s2 = sacc[n][2] * sm_scale;
            float s3 = sacc[n][3] * sm_scale;
            if (need_mask) {
                if (col     > qrow1) s0 = -1e30f;
                if (col + 1 > qrow1) s1 = -1e30f;
                if (col     > qrow2) s2 = -1e30f;
                if (col + 1 > qrow2) s3 = -1e30f;
            }
            sacc[n][0] = s0; sacc[n][1] = s1; sacc[n][2] = s2; sacc[n][3] = s3;
            mx1 = fmaxf(mx1, fmaxf(s0, s1));
            mx2 = fmaxf(mx2, fmaxf(s2, s3));
        }
        mx1 = fmaxf(mx1, __shfl_xor_sync(0xffffffffu, mx1, 1));
        mx1 = fmaxf(mx1, __shfl_xor_sync(0xffffffffu, mx1, 2));
        mx2 = fmaxf(mx2, __shfl_xor_sync(0xffffffffu, mx2, 1));
        mx2 = fmaxf(mx2, __shfl_xor_sync(0xffffffffu, mx2, 2));
        float mn1 = fmaxf(m1, mx1), mn2 = fmaxf(m2, mx2);

        float sum1 = 0.f, sum2 = 0.f;
        uint32_t plo[8], phi[8];
#pragma unroll
        for (int n = 0; n < 8; n++) {
            float p0 = __expf(sacc[n][0] - mn1);
            float p1 = __expf(sacc[n][1] - mn1);
            float p2 = __expf(sacc[n][2] - mn2);
            float p3 = __expf(sacc[n][3] - mn2);
            __half2 hl = __floats2half2_rn(p0, p1);
            __half2 hh = __floats2half2_rn(p2, p3);
            plo[n] = h2_u32(hl);
            phi[n] = h2_u32(hh);
            float2 fl = __half22float2(hl);
            float2 fh = __half22float2(hh);
            sum1 += fl.x + fl.y;
            sum2 += fh.x + fh.y;
        }
        sum1 += __shfl_xor_sync(0xffffffffu, sum1, 1);
        sum1 += __shfl_xor_sync(0xffffffffu, sum1, 2);
        sum2 += __shfl_xor_sync(0xffffffffu, sum2, 1);
        sum2 += __shfl_xor_sync(0xffffffffu, sum2, 2);

        float sc1 = __expf(m1 - mn1), sc2 = __expf(m2 - mn2);
        l1 = l1 * sc1 + sum1;
        l2 = l2 * sc2 + sum2;
        m1 = mn1; m2 = mn2;
#pragma unroll
        for (int n = 0; n < 16; n++) {
            oacc[n][0] *= sc1; oacc[n][1] *= sc1;
            oacc[n][2] *= sc2; oacc[n][3] *= sc2;
        }

        // ---- O += P V  (P fragments straight from registers) ----
#pragma unroll
        for (int sk = 0; sk < 4; sk++) {
            uint32_t a0 = plo[2 * sk], a1 = phi[2 * sk];
            uint32_t a2 = plo[2 * sk + 1], a3 = phi[2 * sk + 1];
#pragma unroll
            for (int j2 = 0; j2 < 8; j2++) {
                uint32_t bb[4];
                ldsm_x4_t(bb, Vb + v_off + (uint32_t)(sk * 16 * KROWH * 2 + j2 * 32));
                mma_f16(oacc[2 * j2],     a0, a1, a2, a3, bb[0], bb[1]);
                mma_f16(oacc[2 * j2 + 1], a0, a1, a2, a3, bb[2], bb[3]);
            }
        }
        __syncthreads();
    }

    // ---- write y (fp16) ----
    float inv1 = 1.0f / l1, inv2 = 1.0f / l2;
    __half* y1 = g_y + ((size_t)b * T_ + qrow1) * D_ + h * HD_;
    __half* y2 = g_y + ((size_t)b * T_ + qrow2) * D_ + h * HD_;
#pragma unroll
    for (int n = 0; n < 16; n++) {
        int col = 8 * n + 2 * cc;
        *(__half2*)(y1 + col) = __floats2half2_rn(oacc[n][0] * inv1, oacc[n][1] * inv1);
        *(__half2*)(y2 + col) = __floats2half2_rn(oacc[n][2] * inv2, oacc[n][3] * inv2);
    }
}

// ============================================================================
extern "C" void kernel_launch(void* const* d_in, const int* in_sizes, int n_in,
                              void* d_out, int out_size)
{
    const float* x     = (const float*)d_in[0];
    const float* w_qkv = (const float*)d_in[1];
    const float* w_out = (const float*)d_in[2];
    float* out = (float*)d_out;

    cudaFuncSetAttribute(attn_kernel, cudaFuncAttributeMaxDynamicSharedMemorySize,
                         ATTN_SMEM_BYTES);

    rope_tab_kernel<<<(T_ * 64 + 255) / 256, 256>>>();

    dim3 g1(6144 / 128, (B_ * T_) / 128);
    gemm_qkv_kernel<<<g1, 256>>>(x, w_qkv);

    dim3 g2(T_ / 128, H_, B_);
    attn_kernel<<<g2, 256, ATTN_SMEM_BYTES>>>();

    dim3 g3(D_ / 128, (B_ * T_) / 128);
    gemm_out_kernel<<<g3, 256>>>(w_out, out);
}

// round 11
// speedup vs baseline: 2.6056x; 1.3199x over previous
#include <cuda_runtime.h>
#include <cuda_fp16.h>
#include <math.h>
#include <stdint.h>

// Problem constants
#define B_  2
#define T_  2048
#define D_  2048
#define H_  16
#define HD_ 128

// ---------------- scratch (static device globals; no allocation) -------------
__device__ __align__(16) __half g_q[(size_t)B_ * H_ * T_ * HD_];   // rope applied
__device__ __align__(16) __half g_k[(size_t)B_ * H_ * T_ * HD_];
__device__ __align__(16) __half g_v[(size_t)B_ * H_ * T_ * HD_];
__device__ __align__(16) __half g_y[(size_t)B_ * T_ * D_];         // attn output
__device__ __align__(16) __half g_xh[(size_t)B_ * T_ * D_];        // x fp16
__device__ __align__(16) __half g_wqh[(size_t)D_ * 3 * HD_ * H_];  // w_qkv fp16
__device__ __align__(16) __half g_woh[(size_t)D_ * D_];            // w_out fp16
__device__ float2 g_rope_tab[T_ * 64];                             // (cos, sin)

// ============================================================================
// helpers
// ============================================================================
__device__ __forceinline__ uint32_t h2_u32(__half2 h) {
    return *reinterpret_cast<uint32_t*>(&h);
}

__device__ __forceinline__ void mma_f16(float c[4],
                                        uint32_t a0, uint32_t a1, uint32_t a2, uint32_t a3,
                                        uint32_t b0, uint32_t b1) {
    asm volatile(
        "mma.sync.aligned.m16n8k16.row.col.f32.f16.f16.f32 "
        "{%0,%1,%2,%3}, {%4,%5,%6,%7}, {%8,%9}, {%0,%1,%2,%3};"
        : "+f"(c[0]), "+f"(c[1]), "+f"(c[2]), "+f"(c[3])
        : "r"(a0), "r"(a1), "r"(a2), "r"(a3), "r"(b0), "r"(b1));
}

__device__ __forceinline__ void ldsm_x4(uint32_t r[4], uint32_t addr) {
    asm volatile("ldmatrix.sync.aligned.m8n8.x4.shared.b16 {%0,%1,%2,%3}, [%4];"
                 : "=r"(r[0]), "=r"(r[1]), "=r"(r[2]), "=r"(r[3]) : "r"(addr));
}
__device__ __forceinline__ void ldsm_x4_t(uint32_t r[4], uint32_t addr) {
    asm volatile("ldmatrix.sync.aligned.m8n8.x4.trans.shared.b16 {%0,%1,%2,%3}, [%4];"
                 : "=r"(r[0]), "=r"(r[1]), "=r"(r[2]), "=r"(r[3]) : "r"(addr));
}

__device__ __forceinline__ void cpa16s(uint32_t saddr, const void* src) {
    asm volatile("cp.async.cg.shared.global [%0], [%1], 16;" :: "r"(saddr), "l"(src));
}
__device__ __forceinline__ void cpa_commit() { asm volatile("cp.async.commit_group;"); }
template<int N> __device__ __forceinline__ void cpa_wait() {
    asm volatile("cp.async.wait_group %0;" :: "n"(N));
}

__device__ __forceinline__ uint32_t smem_u32(const void* p) {
    uint32_t a;
    asm("{ .reg .u64 t; cvta.to.shared.u64 t, %1; cvt.u32.u64 %0, t; }" : "=r"(a) : "l"(p));
    return a;
}

// ============================================================================
// prep kernels (device globals referenced ONLY from device code)
// ============================================================================
__global__ void rope_tab_kernel()
{
    int idx = blockIdx.x * blockDim.x + threadIdx.x;
    if (idx >= T_ * 64) return;
    int t = idx >> 6, i = idx & 63;
    float inv = powf(10000.0f, -((float)(2 * i)) * (1.0f / 128.0f));
    float ang = (float)t * inv;
    float s, c;
    sincosf(ang, &s, &c);
    g_rope_tab[idx] = make_float2(c, s);
}

__device__ __forceinline__ uint2 f4_to_h4(float4 v) {
    return make_uint2(h2_u32(__floats2half2_rn(v.x, v.y)),
                      h2_u32(__floats2half2_rn(v.z, v.w)));
}

__global__ void conv_x_kernel(const float4* __restrict__ in)
{
    int i = blockIdx.x * blockDim.x + threadIdx.x;
    if (i >= B_ * T_ * D_ / 4) return;
    ((uint2*)g_xh)[i] = f4_to_h4(in[i]);
}
__global__ void conv_wq_kernel(const float4* __restrict__ in)
{
    int i = blockIdx.x * blockDim.x + threadIdx.x;
    if (i >= D_ * 3 * HD_ * H_ / 4) return;
    ((uint2*)g_wqh)[i] = f4_to_h4(in[i]);
}
__global__ void conv_wo_kernel(const float4* __restrict__ in)
{
    int i = blockIdx.x * blockDim.x + threadIdx.x;
    if (i >= D_ * D_ / 4) return;
    ((uint2*)g_woh)[i] = f4_to_h4(in[i]);
}

// ============================================================================
// fp16 GEMM 128x128 (k-chunk 32), 256 threads (8 warps 2m x 4n), occ 2.
// 3-stage cp.async pipeline, one __syncthreads per k-chunk.
// ============================================================================
#define AROW 40
#define BROW 136
#define ABUF_BYTES (128 * AROW * 2)                 // 10240
#define BBUF_BYTES (32 * BROW * 2)                  // 8704
#define STAGE_BYTES (ABUF_BYTES + BBUF_BYTES)       // 18944
#define GEMM_SMEM_BYTES (3 * STAGE_BYTES)           // 56832

struct GemmCtx { int m0, n0, lane, warp_m, warp_n; };

template <typename Epi>
__device__ __forceinline__ void gemm_f16_cpa(const __half* __restrict__ A,
                                             const __half* __restrict__ Bg,
                                             int Kd, int Nd, Epi epi)
{
    extern __shared__ __half smg[];
    const uint32_t sb = smem_u32(smg);

    const int tid = threadIdx.x;
    const int lane = tid & 31;
    const int warp = tid >> 5;
    const int warp_m = warp & 1;
    const int warp_n = warp >> 1;
    const int m0 = blockIdx.y * 128;
    const int n0 = blockIdx.x * 128;

    float acc[4][4][4];
#pragma unroll
    for (int mt = 0; mt < 4; mt++)
#pragma unroll
        for (int nt = 0; nt < 4; nt++)
#pragma unroll
            for (int e = 0; e < 4; e++) acc[mt][nt][e] = 0.f;

    const uint32_t a_off =
        (uint32_t)((warp_m * 64 + (lane & 7) + ((lane >> 3) & 1) * 8) * AROW +
                   (lane >> 4) * 8) * 2;
    const uint32_t b_off = (uint32_t)ABUF_BYTES +
        (uint32_t)(((lane & 7) + ((lane >> 3) & 1) * 8) * BROW +
                   warp_n * 32 + (lane >> 4) * 8) * 2;

#define LOADG(it, stage)                                                          \
    {                                                                             \
        uint32_t ab = sb + (stage) * STAGE_BYTES;                                 \
        uint32_t bb = ab + ABUF_BYTES;                                            \
        int kk = (it) * 32;                                                       \
        _Pragma("unroll")                                                         \
        for (int i = 0; i < 2; i++) {                                             \
            int idx = tid + 256 * i;                                              \
            int row = idx >> 2, c = idx & 3;                                      \
            cpa16s(ab + (uint32_t)(row * (AROW * 2) + c * 16),                    \
                   A + (size_t)(m0 + row) * Kd + kk + c * 8);                     \
        }                                                                         \
        _Pragma("unroll")                                                         \
        for (int i = 0; i < 2; i++) {                                             \
            int idx = tid + 256 * i;                                              \
            int row = idx >> 4, c = idx & 15;                                     \
            cpa16s(bb + (uint32_t)(row * (BROW * 2) + c * 16),                    \
                   Bg + (size_t)(kk + row) * Nd + n0 + c * 8);                    \
        }                                                                         \
        cpa_commit();                                                             \
    }

    const int nt = Kd / 32;
    LOADG(0, 0);
    LOADG(1, 1);

    for (int it = 0; it < nt; it++) {
        if (it + 1 < nt) cpa_wait<1>(); else cpa_wait<0>();
        __syncthreads();   // stage(it) visible; reads of stage((it+2)%3) finished

        if (it + 2 < nt) LOADG(it + 2, (it + 2) % 3);

        const uint32_t base = sb + (it % 3) * STAGE_BYTES;
#pragma unroll
        for (int s = 0; s < 2; s++) {
            uint32_t af[4][4];
#pragma unroll
            for (int mt = 0; mt < 4; mt++)
                ldsm_x4(af[mt], base + a_off + (uint32_t)(mt * 16 * AROW * 2 + s * 32));
            uint32_t bf[2][4];
#pragma unroll
            for (int nt2 = 0; nt2 < 2; nt2++)
                ldsm_x4_t(bf[nt2], base + b_off + (uint32_t)(s * 16 * BROW * 2 + nt2 * 32));
#pragma unroll
            for (int mt = 0; mt < 4; mt++)
#pragma unroll
                for (int ntv = 0; ntv < 4; ntv++)
                    mma_f16(acc[mt][ntv],
                            af[mt][0], af[mt][1], af[mt][2], af[mt][3],
                            bf[ntv >> 1][(ntv & 1) * 2], bf[ntv >> 1][(ntv & 1) * 2 + 1]);
        }
    }
#undef LOADG

    GemmCtx ctx{m0, n0, lane, warp_m, warp_n};
    epi(ctx, acc);
}

// ---------------- epilogues --------------------------------------------------
__device__ __forceinline__ void qkv_scatter_pair(int row, int col, float v0, float v1)
{
    int b = row >> 11, t = row & (T_ - 1);
    int h = col / (3 * HD_);
    int r = col % (3 * HD_);                 // always even
    size_t base = (((size_t)(b * H_ + h)) * T_ + t) * HD_;
    if (r < 2 * HD_) {
        __half* dst = (r < HD_) ? g_q : g_k;
        int rr = r & (HD_ - 1);
        float2 cs = g_rope_tab[(t << 6) + (rr >> 1)];
        float o0 = v0 * cs.x - v1 * cs.y;
        float o1 = v0 * cs.y + v1 * cs.x;
        *(__half2*)&dst[base + rr] = __floats2half2_rn(o0, o1);
    } else {
        *(__half2*)&g_v[base + r - 2 * HD_] = __floats2half2_rn(v0, v1);
    }
}

struct QkvEpi {
    __device__ __forceinline__ void operator()(const GemmCtx& c, float acc[4][4][4]) const {
#pragma unroll
        for (int mt = 0; mt < 4; mt++) {
            int row = c.m0 + c.warp_m * 64 + mt * 16 + (c.lane >> 2);
#pragma unroll
            for (int nt = 0; nt < 4; nt++) {
                int col = c.n0 + c.warp_n * 32 + nt * 8 + (c.lane & 3) * 2;
                qkv_scatter_pair(row,     col, acc[mt][nt][0], acc[mt][nt][1]);
                qkv_scatter_pair(row + 8, col, acc[mt][nt][2], acc[mt][nt][3]);
            }
        }
    }
};

struct OutEpi {
    float* C;
    __device__ __forceinline__ void operator()(const GemmCtx& c, float acc[4][4][4]) const {
#pragma unroll
        for (int mt = 0; mt < 4; mt++) {
            int row = c.m0 + c.warp_m * 64 + mt * 16 + (c.lane >> 2);
#pragma unroll
            for (int nt = 0; nt < 4; nt++) {
                int col = c.n0 + c.warp_n * 32 + nt * 8 + (c.lane & 3) * 2;
                *(float2*)(C + (size_t)row * D_ + col) =
                    make_float2(acc[mt][nt][0], acc[mt][nt][1]);
                *(float2*)(C + (size_t)(row + 8) * D_ + col) =
                    make_float2(acc[mt][nt][2], acc[mt][nt][3]);
            }
        }
    }
};

__global__ __launch_bounds__(256, 2) void gemm_qkv_kernel()
{
    gemm_f16_cpa(g_xh, g_wqh, D_, 3 * HD_ * H_, QkvEpi{});
}

__global__ __launch_bounds__(256, 2) void gemm_out_kernel(float* __restrict__ C)
{
    gemm_f16_cpa(g_y, g_woh, D_, D_, OutEpi{C});
}

// ============================================================================
// Flash attention, fp16 mma.m16n8k16 (round-9 body, unchanged).
// ============================================================================
#define KROWH 136
#define KV_TILE_BYTES (64 * KROWH * 2)          // 17408
#define ATTN_SMEM_BYTES (4 * KV_TILE_BYTES)     // 69632

__device__ __forceinline__ void load_kv(uint32_t sm_u, int buf,
                                        const __half* Kh, const __half* Vh,
                                        int k0, int tid)
{
    uint32_t kb = sm_u + buf * KV_TILE_BYTES;
    uint32_t vb = sm_u + 2 * KV_TILE_BYTES + buf * KV_TILE_BYTES;
#pragma unroll
    for (int i = 0; i < 4; i++) {
        int idx = tid + i * 256;
        int row = idx >> 4, c16 = idx & 15;
        cpa16s(kb + row * (KROWH * 2) + c16 * 16,
               Kh + (size_t)(k0 + row) * HD_ + c16 * 8);
    }
#pragma unroll
    for (int i = 0; i < 4; i++) {
        int idx = tid + i * 256;
        int row = idx >> 4, c16 = idx & 15;
        cpa16s(vb + row * (KROWH * 2) + c16 * 16,
               Vh + (size_t)(k0 + row) * HD_ + c16 * 8);
    }
    cpa_commit();
}

__global__ __launch_bounds__(256, 1) void attn_kernel()
{
    extern __shared__ __half smh[];
    const uint32_t sm_u = smem_u32(smh);

    const int b = blockIdx.z, h = blockIdx.y;
    const int q0 = blockIdx.x * 128;
    const __half* Qh = g_q + (((size_t)(b * H_ + h)) * T_) * HD_;
    const __half* Kh = g_k + (((size_t)(b * H_ + h)) * T_) * HD_;
    const __half* Vh = g_v + (((size_t)(b * H_ + h)) * T_) * HD_;

    const int tid = threadIdx.x;
    const int lane = tid & 31;
    const int w = tid >> 5;
    const int r1 = lane >> 2;
    const int cc = lane & 3;
    const int qrow1 = q0 + w * 16 + r1;
    const int qrow2 = qrow1 + 8;
    const int ntile = (q0 >> 6) + 2;

    load_kv(sm_u, 0, Kh, Vh, 0, tid);

    uint32_t qf[8][4];
#pragma unroll
    for (int s = 0; s < 8; s++) {
        qf[s][0] = *(const uint32_t*)(Qh + (size_t)qrow1 * HD_ + 16 * s + 2 * cc);
        qf[s][1] = *(const uint32_t*)(Qh + (size_t)qrow2 * HD_ + 16 * s + 2 * cc);
        qf[s][2] = *(const uint32_t*)(Qh + (size_t)qrow1 * HD_ + 16 * s + 8 + 2 * cc);
        qf[s][3] = *(const uint32_t*)(Qh + (size_t)qrow2 * HD_ + 16 * s + 8 + 2 * cc);
    }

    float oacc[16][4];
#pragma unroll
    for (int n = 0; n < 16; n++)
#pragma unroll
        for (int e = 0; e < 4; e++) oacc[n][e] = 0.f;
    float m1 = -1e30f, m2 = -1e30f, l1 = 0.f, l2 = 0.f;
    const float sm_scale = 0.08838834764831845f;

    const uint32_t k_off =
        (uint32_t)(((lane & 7) + (lane >> 4) * 8) * KROWH + ((lane >> 3) & 1) * 8) * 2;
    const uint32_t v_off =
        (uint32_t)(((lane & 7) + ((lane >> 3) & 1) * 8) * KROWH + (lane >> 4) * 8) * 2;

    for (int t = 0; t < ntile; t++) {
        const int k0 = t * 64;
        const uint32_t Kb = sm_u + (t & 1) * KV_TILE_BYTES;
        const uint32_t Vb = sm_u + 2 * KV_TILE_BYTES + (t & 1) * KV_TILE_BYTES;

        if (t + 1 < ntile) {
            load_kv(sm_u, (t + 1) & 1, Kh, Vh, k0 + 64, tid);
            cpa_wait<1>();
        } else {
            cpa_wait<0>();
        }
        __syncthreads();

        float sacc[8][4];
#pragma unroll
        for (int n = 0; n < 8; n++)
#pragma unroll
            for (int e = 0; e < 4; e++) sacc[n][e] = 0.f;

#pragma unroll
        for (int s = 0; s < 8; s++) {
#pragma unroll
            for (int j = 0; j < 4; j++) {
                uint32_t bb[4];
                ldsm_x4(bb, Kb + k_off + (uint32_t)(j * 16 * KROWH * 2 + s * 32));
                mma_f16(sacc[2 * j],     qf[s][0], qf[s][1], qf[s][2], qf[s][3], bb[0], bb[1]);
                mma_f16(sacc[2 * j + 1], qf[s][0], qf[s][1], qf[s][2], qf[s][3], bb[2], bb[3]);
            }
        }

        const bool need_mask = (t >= ntile - 2);
        float mx1 = -1e30f, mx2 = -1e30f;
#pragma unroll
        for (int n = 0; n < 8; n++) {
            int col = k0 + 8 * n + 2 * cc;
            float s0 = sacc[n][0] * sm_scale;
            float s1 = sacc[n][1] * sm_scale;
            float s2 = sacc[n][2] * sm_scale;
            float s3 = sacc[n][3] * sm_scale;
            if (need_mask) {
                if (col     > qrow1) s0 = -1e30f;
                if (col + 1 > qrow1) s1 = -1e30f;
                if (col     > qrow2) s2 = -1e30f;
                if (col + 1 > qrow2) s3 = -1e30f;
            }
            sacc[n][0] = s0; sacc[n][1] = s1; sacc[n][2] = s2; sacc[n][3] = s3;
            mx1 = fmaxf(mx1, fmaxf(s0, s1));
            mx2 = fmaxf(mx2, fmaxf(s2, s3));
        }
        mx1 = fmaxf(mx1, __shfl_xor_sync(0xffffffffu, mx1, 1));
        mx1 = fmaxf(mx1, __shfl_xor_sync(0xffffffffu, mx1, 2));
        mx2 = fmaxf(mx2, __shfl_xor_sync(0xffffffffu, mx2, 1));
        mx2 = fmaxf(mx2, __shfl_xor_sync(0xffffffffu, mx2, 2));
        float mn1 = fmaxf(m1, mx1), mn2 = fmaxf(m2, mx2);

        float sum1 = 0.f, sum2 = 0.f;
        uint32_t plo[8], phi[8];
#pragma unroll
        for (int n = 0; n < 8; n++) {
            float p0 = __expf(sacc[n][0] - mn1);
            float p1 = __expf(sacc[n][1] - mn1);
            float p2 = __expf(sacc[n][2] - mn2);
            float p3 = __expf(sacc[n][3] - mn2);
            __half2 hl = __floats2half2_rn(p0, p1);
            __half2 hh = __floats2half2_rn(p2, p3);
            plo[n] = h2_u32(hl);
            phi[n] = h2_u32(hh);
            float2 fl = __half22float2(hl);
            float2 fh = __half22float2(hh);
            sum1 += fl.x + fl.y;
            sum2 += fh.x + fh.y;
        }
        sum1 += __shfl_xor_sync(0xffffffffu, sum1, 1);
        sum1 += __shfl_xor_sync(0xffffffffu, sum1, 2);
        sum2 += __shfl_xor_sync(0xffffffffu, sum2, 1);
        sum2 += __shfl_xor_sync(0xffffffffu, sum2, 2);

        float sc1 = __expf(m1 - mn1), sc2 = __expf(m2 - mn2);
        l1 = l1 * sc1 + sum1;
        l2 = l2 * sc2 + sum2;
        m1 = mn1; m2 = mn2;
#pragma unroll
        for (int n = 0; n < 16; n++) {
            oacc[n][0] *= sc1; oacc[n][1] *= sc1;
            oacc[n][2] *= sc2; oacc[n][3] *= sc2;
        }

#pragma unroll
        for (int sk = 0; sk < 4; sk++) {
            uint32_t a0 = plo[2 * sk], a1 = phi[2 * sk];
            uint32_t a2 = plo[2 * sk + 1], a3 = phi[2 * sk + 1];
#pragma unroll
            for (int j2 = 0; j2 < 8; j2++) {
                uint32_t bb[4];
                ldsm_x4_t(bb, Vb + v_off + (uint32_t)(sk * 16 * KROWH * 2 + j2 * 32));
                mma_f16(oacc[2 * j2],     a0, a1, a2, a3, bb[0], bb[1]);
                mma_f16(oacc[2 * j2 + 1], a0, a1, a2, a3, bb[2], bb[3]);
            }
        }
        __syncthreads();
    }

    float inv1 = 1.0f / l1, inv2 = 1.0f / l2;
    __half* y1 = g_y + ((size_t)b * T_ + qrow1) * D_ + h * HD_;
    __half* y2 = g_y + ((size_t)b * T_ + qrow2) * D_ + h * HD_;
#pragma unroll
    for (int n = 0; n < 16; n++) {
        int col = 8 * n + 2 * cc;
        *(__half2*)(y1 + col) = __floats2half2_rn(oacc[n][0] * inv1, oacc[n][1] * inv1);
        *(__half2*)(y2 + col) = __floats2half2_rn(oacc[n][2] * inv2, oacc[n][3] * inv2);
    }
}

// ============================================================================
extern "C" void kernel_launch(void* const* d_in, const int* in_sizes, int n_in,
                              void* d_out, int out_size)
{
    const float* x     = (const float*)d_in[0];
    const float* w_qkv = (const float*)d_in[1];
    const float* w_out = (const float*)d_in[2];
    float* out = (float*)d_out;

    cudaFuncSetAttribute(attn_kernel, cudaFuncAttributeMaxDynamicSharedMemorySize,
                         ATTN_SMEM_BYTES);
    cudaFuncSetAttribute(gemm_qkv_kernel, cudaFuncAttributeMaxDynamicSharedMemorySize,
                         GEMM_SMEM_BYTES);
    cudaFuncSetAttribute(gemm_out_kernel, cudaFuncAttributeMaxDynamicSharedMemorySize,
                         GEMM_SMEM_BYTES);

    rope_tab_kernel<<<(T_ * 64 + 255) / 256, 256>>>();
    conv_x_kernel<<<((B_ * T_ * D_ / 4) + 255) / 256, 256>>>((const float4*)x);
    conv_wq_kernel<<<((D_ * 3 * HD_ * H_ / 4) + 255) / 256, 256>>>((const float4*)w_qkv);
    conv_wo_kernel<<<((D_ * D_ / 4) + 255) / 256, 256>>>((const float4*)w_out);

    dim3 g1(6144 / 128, (B_ * T_) / 128);
    gemm_qkv_kernel<<<g1, 256, GEMM_SMEM_BYTES>>>();

    dim3 g2(T_ / 128, H_, B_);
    attn_kernel<<<g2, 256, ATTN_SMEM_BYTES>>>();

    dim3 g3(D_ / 128, (B_ * T_) / 128);
    gemm_out_kernel<<<g3, 256, GEMM_SMEM_BYTES>>>(out);
}

// round 12
// speedup vs baseline: 2.7179x; 1.0431x over previous
#include <cuda_runtime.h>
#include <cuda_fp16.h>
#include <math.h>
#include <stdint.h>

// Problem constants
#define B_  2
#define T_  2048
#define D_  2048
#define H_  16
#define HD_ 128

// ---------------- scratch (static device globals; no allocation) -------------
__device__ __align__(16) __half g_q[(size_t)B_ * H_ * T_ * HD_];   // rope applied
__device__ __align__(16) __half g_k[(size_t)B_ * H_ * T_ * HD_];
__device__ __align__(16) __half g_v[(size_t)B_ * H_ * T_ * HD_];
__device__ __align__(16) __half g_y[(size_t)B_ * T_ * D_];         // attn output
__device__ __align__(16) __half g_xh[(size_t)B_ * T_ * D_];        // x fp16
__device__ __align__(16) __half g_wqh[(size_t)D_ * 3 * HD_ * H_];  // w_qkv fp16
__device__ __align__(16) __half g_woh[(size_t)D_ * D_];            // w_out fp16
__device__ float2 g_rope_tab[T_ * 64];                             // (cos, sin)

// ============================================================================
// helpers
// ============================================================================
__device__ __forceinline__ uint32_t h2_u32(__half2 h) {
    return *reinterpret_cast<uint32_t*>(&h);
}

__device__ __forceinline__ void mma_f16(float c[4],
                                        uint32_t a0, uint32_t a1, uint32_t a2, uint32_t a3,
                                        uint32_t b0, uint32_t b1) {
    asm volatile(
        "mma.sync.aligned.m16n8k16.row.col.f32.f16.f16.f32 "
        "{%0,%1,%2,%3}, {%4,%5,%6,%7}, {%8,%9}, {%0,%1,%2,%3};"
        : "+f"(c[0]), "+f"(c[1]), "+f"(c[2]), "+f"(c[3])
        : "r"(a0), "r"(a1), "r"(a2), "r"(a3), "r"(b0), "r"(b1));
}

__device__ __forceinline__ void ldsm_x4(uint32_t r[4], uint32_t addr) {
    asm volatile("ldmatrix.sync.aligned.m8n8.x4.shared.b16 {%0,%1,%2,%3}, [%4];"
                 : "=r"(r[0]), "=r"(r[1]), "=r"(r[2]), "=r"(r[3]) : "r"(addr));
}
__device__ __forceinline__ void ldsm_x4_t(uint32_t r[4], uint32_t addr) {
    asm volatile("ldmatrix.sync.aligned.m8n8.x4.trans.shared.b16 {%0,%1,%2,%3}, [%4];"
                 : "=r"(r[0]), "=r"(r[1]), "=r"(r[2]), "=r"(r[3]) : "r"(addr));
}

__device__ __forceinline__ void cpa16s(uint32_t saddr, const void* src) {
    asm volatile("cp.async.cg.shared.global [%0], [%1], 16;" :: "r"(saddr), "l"(src));
}
__device__ __forceinline__ void cpa_commit() { asm volatile("cp.async.commit_group;"); }
template<int N> __device__ __forceinline__ void cpa_wait() {
    asm volatile("cp.async.wait_group %0;" :: "n"(N));
}

__device__ __forceinline__ uint32_t smem_u32(const void* p) {
    uint32_t a;
    asm("{ .reg .u64 t; cvta.to.shared.u64 t, %1; cvt.u32.u64 %0, t; }" : "=r"(a) : "l"(p));
    return a;
}

// ============================================================================
// prep kernels (device globals referenced ONLY from device code)
// ============================================================================
__global__ void rope_tab_kernel()
{
    int idx = blockIdx.x * blockDim.x + threadIdx.x;
    if (idx >= T_ * 64) return;
    int t = idx >> 6, i = idx & 63;
    float inv = powf(10000.0f, -((float)(2 * i)) * (1.0f / 128.0f));
    float ang = (float)t * inv;
    float s, c;
    sincosf(ang, &s, &c);
    g_rope_tab[idx] = make_float2(c, s);
}

__device__ __forceinline__ uint2 f4_to_h4(float4 v) {
    return make_uint2(h2_u32(__floats2half2_rn(v.x, v.y)),
                      h2_u32(__floats2half2_rn(v.z, v.w)));
}

__global__ void conv_x_kernel(const float4* __restrict__ in)
{
    int i = blockIdx.x * blockDim.x + threadIdx.x;
    if (i >= B_ * T_ * D_ / 4) return;
    ((uint2*)g_xh)[i] = f4_to_h4(in[i]);
}
__global__ void conv_wq_kernel(const float4* __restrict__ in)
{
    int i = blockIdx.x * blockDim.x + threadIdx.x;
    if (i >= D_ * 3 * HD_ * H_ / 4) return;
    ((uint2*)g_wqh)[i] = f4_to_h4(in[i]);
}
__global__ void conv_wo_kernel(const float4* __restrict__ in)
{
    int i = blockIdx.x * blockDim.x + threadIdx.x;
    if (i >= D_ * D_ / 4) return;
    ((uint2*)g_woh)[i] = f4_to_h4(in[i]);
}

// ============================================================================
// fp16 GEMM 128x128 (k-chunk 32), 256 threads (8 warps 2m x 4n), occ 2.
// 4-stage cp.async pipeline, one __syncthreads per k-chunk.
// ============================================================================
#define AROW 40
#define BROW 136
#define ABUF_BYTES (128 * AROW * 2)                 // 10240
#define BBUF_BYTES (32 * BROW * 2)                  // 8704
#define STAGE_BYTES (ABUF_BYTES + BBUF_BYTES)       // 18944
#define GEMM_SMEM_BYTES (4 * STAGE_BYTES)           // 75776

struct GemmCtx { int m0, n0, lane, warp_m, warp_n; };

template <typename Epi>
__device__ __forceinline__ void gemm_f16_cpa(const __half* __restrict__ A,
                                             const __half* __restrict__ Bg,
                                             int Kd, int Nd, Epi epi)
{
    extern __shared__ __half smg[];
    const uint32_t sb = smem_u32(smg);

    const int tid = threadIdx.x;
    const int lane = tid & 31;
    const int warp = tid >> 5;
    const int warp_m = warp & 1;
    const int warp_n = warp >> 1;
    const int m0 = blockIdx.y * 128;
    const int n0 = blockIdx.x * 128;

    float acc[4][4][4];
#pragma unroll
    for (int mt = 0; mt < 4; mt++)
#pragma unroll
        for (int nt = 0; nt < 4; nt++)
#pragma unroll
            for (int e = 0; e < 4; e++) acc[mt][nt][e] = 0.f;

    const uint32_t a_off =
        (uint32_t)((warp_m * 64 + (lane & 7) + ((lane >> 3) & 1) * 8) * AROW +
                   (lane >> 4) * 8) * 2;
    const uint32_t b_off = (uint32_t)ABUF_BYTES +
        (uint32_t)(((lane & 7) + ((lane >> 3) & 1) * 8) * BROW +
                   warp_n * 32 + (lane >> 4) * 8) * 2;

#define LOADG(it, stage)                                                          \
    {                                                                             \
        uint32_t ab = sb + (stage) * STAGE_BYTES;                                 \
        uint32_t bb = ab + ABUF_BYTES;                                            \
        int kk = (it) * 32;                                                       \
        _Pragma("unroll")                                                         \
        for (int i = 0; i < 2; i++) {                                             \
            int idx = tid + 256 * i;                                              \
            int row = idx >> 2, c = idx & 3;                                      \
            cpa16s(ab + (uint32_t)(row * (AROW * 2) + c * 16),                    \
                   A + (size_t)(m0 + row) * Kd + kk + c * 8);                     \
        }                                                                         \
        _Pragma("unroll")                                                         \
        for (int i = 0; i < 2; i++) {                                             \
            int idx = tid + 256 * i;                                              \
            int row = idx >> 4, c = idx & 15;                                     \
            cpa16s(bb + (uint32_t)(row * (BROW * 2) + c * 16),                    \
                   Bg + (size_t)(kk + row) * Nd + n0 + c * 8);                    \
        }                                                                         \
        cpa_commit();                                                             \
    }

    const int nt = Kd / 32;   // 64
    LOADG(0, 0);
    LOADG(1, 1);
    LOADG(2, 2);

    for (int it = 0; it < nt; it++) {
        // stage(it) must be complete; groups complete in order.
        if (it + 2 < nt)      cpa_wait<2>();
        else if (it + 1 < nt) cpa_wait<1>();
        else                  cpa_wait<0>();
        __syncthreads();   // stage(it) visible; compute of stage((it+3)%4) finished in it-1

        if (it + 3 < nt) LOADG(it + 3, (it + 3) & 3);

        const uint32_t base = sb + (it & 3) * STAGE_BYTES;
#pragma unroll
        for (int s = 0; s < 2; s++) {
            uint32_t af[4][4];
#pragma unroll
            for (int mt = 0; mt < 4; mt++)
                ldsm_x4(af[mt], base + a_off + (uint32_t)(mt * 16 * AROW * 2 + s * 32));
            uint32_t bf[2][4];
#pragma unroll
            for (int nt2 = 0; nt2 < 2; nt2++)
                ldsm_x4_t(bf[nt2], base + b_off + (uint32_t)(s * 16 * BROW * 2 + nt2 * 32));
#pragma unroll
            for (int mt = 0; mt < 4; mt++)
#pragma unroll
                for (int ntv = 0; ntv < 4; ntv++)
                    mma_f16(acc[mt][ntv],
                            af[mt][0], af[mt][1], af[mt][2], af[mt][3],
                            bf[ntv >> 1][(ntv & 1) * 2], bf[ntv >> 1][(ntv & 1) * 2 + 1]);
        }
    }
#undef LOADG

    GemmCtx ctx{m0, n0, lane, warp_m, warp_n};
    epi(ctx, acc);
}

// ---------------- epilogues --------------------------------------------------
__device__ __forceinline__ void qkv_scatter_pair(int row, int col, float v0, float v1)
{
    int b = row >> 11, t = row & (T_ - 1);
    int h = col / (3 * HD_);
    int r = col % (3 * HD_);                 // always even
    size_t base = (((size_t)(b * H_ + h)) * T_ + t) * HD_;
    if (r < 2 * HD_) {
        __half* dst = (r < HD_) ? g_q : g_k;
        int rr = r & (HD_ - 1);
        float2 cs = g_rope_tab[(t << 6) + (rr >> 1)];
        float o0 = v0 * cs.x - v1 * cs.y;
        float o1 = v0 * cs.y + v1 * cs.x;
        *(__half2*)&dst[base + rr] = __floats2half2_rn(o0, o1);
    } else {
        *(__half2*)&g_v[base + r - 2 * HD_] = __floats2half2_rn(v0, v1);
    }
}

struct QkvEpi {
    __device__ __forceinline__ void operator()(const GemmCtx& c, float acc[4][4][4]) const {
#pragma unroll
        for (int mt = 0; mt < 4; mt++) {
            int row = c.m0 + c.warp_m * 64 + mt * 16 + (c.lane >> 2);
#pragma unroll
            for (int nt = 0; nt < 4; nt++) {
                int col = c.n0 + c.warp_n * 32 + nt * 8 + (c.lane & 3) * 2;
                qkv_scatter_pair(row,     col, acc[mt][nt][0], acc[mt][nt][1]);
                qkv_scatter_pair(row + 8, col, acc[mt][nt][2], acc[mt][nt][3]);
            }
        }
    }
};

struct OutEpi {
    float* C;
    __device__ __forceinline__ void operator()(const GemmCtx& c, float acc[4][4][4]) const {
#pragma unroll
        for (int mt = 0; mt < 4; mt++) {
            int row = c.m0 + c.warp_m * 64 + mt * 16 + (c.lane >> 2);
#pragma unroll
            for (int nt = 0; nt < 4; nt++) {
                int col = c.n0 + c.warp_n * 32 + nt * 8 + (c.lane & 3) * 2;
                *(float2*)(C + (size_t)row * D_ + col) =
                    make_float2(acc[mt][nt][0], acc[mt][nt][1]);
                *(float2*)(C + (size_t)(row + 8) * D_ + col) =
                    make_float2(acc[mt][nt][2], acc[mt][nt][3]);
            }
        }
    }
};

__global__ __launch_bounds__(256, 2) void gemm_qkv_kernel()
{
    gemm_f16_cpa(g_xh, g_wqh, D_, 3 * HD_ * H_, QkvEpi{});
}

__global__ __launch_bounds__(256, 2) void gemm_out_kernel(float* __restrict__ C)
{
    gemm_f16_cpa(g_y, g_woh, D_, D_, OutEpi{C});
}

// ============================================================================
// Flash attention, fp16 mma.m16n8k16 (round-9 body) + reversed tile order
// for causal load balance (longest CTAs launch first).
// ============================================================================
#define KROWH 136
#define KV_TILE_BYTES (64 * KROWH * 2)          // 17408
#define ATTN_SMEM_BYTES (4 * KV_TILE_BYTES)     // 69632

__device__ __forceinline__ void load_kv(uint32_t sm_u, int buf,
                                        const __half* Kh, const __half* Vh,
                                        int k0, int tid)
{
    uint32_t kb = sm_u + buf * KV_TILE_BYTES;
    uint32_t vb = sm_u + 2 * KV_TILE_BYTES + buf * KV_TILE_BYTES;
#pragma unroll
    for (int i = 0; i < 4; i++) {
        int idx = tid + i * 256;
        int row = idx >> 4, c16 = idx & 15;
        cpa16s(kb + row * (KROWH * 2) + c16 * 16,
               Kh + (size_t)(k0 + row) * HD_ + c16 * 8);
    }
#pragma unroll
    for (int i = 0; i < 4; i++) {
        int idx = tid + i * 256;
        int row = idx >> 4, c16 = idx & 15;
        cpa16s(vb + row * (KROWH * 2) + c16 * 16,
               Vh + (size_t)(k0 + row) * HD_ + c16 * 8);
    }
    cpa_commit();
}

__global__ __launch_bounds__(256, 1) void attn_kernel()
{
    extern __shared__ __half smh[];
    const uint32_t sm_u = smem_u32(smh);

    const int b = blockIdx.z, h = blockIdx.y;
    const int q0 = ((int)gridDim.x - 1 - (int)blockIdx.x) * 128;  // longest first
    const __half* Qh = g_q + (((size_t)(b * H_ + h)) * T_) * HD_;
    const __half* Kh = g_k + (((size_t)(b * H_ + h)) * T_) * HD_;
    const __half* Vh = g_v + (((size_t)(b * H_ + h)) * T_) * HD_;

    const int tid = threadIdx.x;
    const int lane = tid & 31;
    const int w = tid >> 5;
    const int r1 = lane >> 2;
    const int cc = lane & 3;
    const int qrow1 = q0 + w * 16 + r1;
    const int qrow2 = qrow1 + 8;
    const int ntile = (q0 >> 6) + 2;

    load_kv(sm_u, 0, Kh, Vh, 0, tid);

    uint32_t qf[8][4];
#pragma unroll
    for (int s = 0; s < 8; s++) {
        qf[s][0] = *(const uint32_t*)(Qh + (size_t)qrow1 * HD_ + 16 * s + 2 * cc);
        qf[s][1] = *(const uint32_t*)(Qh + (size_t)qrow2 * HD_ + 16 * s + 2 * cc);
        qf[s][2] = *(const uint32_t*)(Qh + (size_t)qrow1 * HD_ + 16 * s + 8 + 2 * cc);
        qf[s][3] = *(const uint32_t*)(Qh + (size_t)qrow2 * HD_ + 16 * s + 8 + 2 * cc);
    }

    float oacc[16][4];
#pragma unroll
    for (int n = 0; n < 16; n++)
#pragma unroll
        for (int e = 0; e < 4; e++) oacc[n][e] = 0.f;
    float m1 = -1e30f, m2 = -1e30f, l1 = 0.f, l2 = 0.f;
    const float sm_scale = 0.08838834764831845f;

    const uint32_t k_off =
        (uint32_t)(((lane & 7) + (lane >> 4) * 8) * KROWH + ((lane >> 3) & 1) * 8) * 2;
    const uint32_t v_off =
        (uint32_t)(((lane & 7) + ((lane >> 3) & 1) * 8) * KROWH + (lane >> 4) * 8) * 2;

    for (int t = 0; t < ntile; t++) {
        const int k0 = t * 64;
        const uint32_t Kb = sm_u + (t & 1) * KV_TILE_BYTES;
        const uint32_t Vb = sm_u + 2 * KV_TILE_BYTES + (t & 1) * KV_TILE_BYTES;

        if (t + 1 < ntile) {
            load_kv(sm_u, (t + 1) & 1, Kh, Vh, k0 + 64, tid);
            cpa_wait<1>();
        } else {
            cpa_wait<0>();
        }
        __syncthreads();

        float sacc[8][4];
#pragma unroll
        for (int n = 0; n < 8; n++)
#pragma unroll
            for (int e = 0; e < 4; e++) sacc[n][e] = 0.f;

#pragma unroll
        for (int s = 0; s < 8; s++) {
#pragma unroll
            for (int j = 0; j < 4; j++) {
                uint32_t bb[4];
                ldsm_x4(bb, Kb + k_off + (uint32_t)(j * 16 * KROWH * 2 + s * 32));
                mma_f16(sacc[2 * j],     qf[s][0], qf[s][1], qf[s][2], qf[s][3], bb[0], bb[1]);
                mma_f16(sacc[2 * j + 1], qf[s][0], qf[s][1], qf[s][2], qf[s][3], bb[2], bb[3]);
            }
        }

        const bool need_mask = (t >= ntile - 2);
        float mx1 = -1e30f, mx2 = -1e30f;
#pragma unroll
        for (int n = 0; n < 8; n++) {
            int col = k0 + 8 * n + 2 * cc;
            float s0 = sacc[n][0] * sm_scale;
            float s1 = sacc[n][1] * sm_scale;
            float s2 = sacc[n][2] * sm_scale;
            float s3 = sacc[n][3] * sm_scale;
            if (need_mask) {
                if (col     > qrow1) s0 = -1e30f;
                if (col + 1 > qrow1) s1 = -1e30f;
                if (col     > qrow2) s2 = -1e30f;
                if (col + 1 > qrow2) s3 = -1e30f;
            }
            sacc[n][0] = s0; sacc[n][1] = s1; sacc[n][2] = s2; sacc[n][3] = s3;
            mx1 = fmaxf(mx1, fmaxf(s0, s1));
            mx2 = fmaxf(mx2, fmaxf(s2, s3));
        }
        mx1 = fmaxf(mx1, __shfl_xor_sync(0xffffffffu, mx1, 1));
        mx1 = fmaxf(mx1, __shfl_xor_sync(0xffffffffu, mx1, 2));
        mx2 = fmaxf(mx2, __shfl_xor_sync(0xffffffffu, mx2, 1));
        mx2 = fmaxf(mx2, __shfl_xor_sync(0xffffffffu, mx2, 2));
        float mn1 = fmaxf(m1, mx1), mn2 = fmaxf(m2, mx2);

        float sum1 = 0.f, sum2 = 0.f;
        uint32_t plo[8], phi[8];
#pragma unroll
        for (int n = 0; n < 8; n++) {
            float p0 = __expf(sacc[n][0] - mn1);
            float p1 = __expf(sacc[n][1] - mn1);
            float p2 = __expf(sacc[n][2] - mn2);
            float p3 = __expf(sacc[n][3] - mn2);
            __half2 hl = __floats2half2_rn(p0, p1);
            __half2 hh = __floats2half2_rn(p2, p3);
            plo[n] = h2_u32(hl);
            phi[n] = h2_u32(hh);
            float2 fl = __half22float2(hl);
            float2 fh = __half22float2(hh);
            sum1 += fl.x + fl.y;
            sum2 += fh.x + fh.y;
        }
        sum1 += __shfl_xor_sync(0xffffffffu, sum1, 1);
        sum1 += __shfl_xor_sync(0xffffffffu, sum1, 2);
        sum2 += __shfl_xor_sync(0xffffffffu, sum2, 1);
        sum2 += __shfl_xor_sync(0xffffffffu, sum2, 2);

        float sc1 = __expf(m1 - mn1), sc2 = __expf(m2 - mn2);
        l1 = l1 * sc1 + sum1;
        l2 = l2 * sc2 + sum2;
        m1 = mn1; m2 = mn2;
#pragma unroll
        for (int n = 0; n < 16; n++) {
            oacc[n][0] *= sc1; oacc[n][1] *= sc1;
            oacc[n][2] *= sc2; oacc[n][3] *= sc2;
        }

#pragma unroll
        for (int sk = 0; sk < 4; sk++) {
            uint32_t a0 = plo[2 * sk], a1 = phi[2 * sk];
            uint32_t a2 = plo[2 * sk + 1], a3 = phi[2 * sk + 1];
#pragma unroll
            for (int j2 = 0; j2 < 8; j2++) {
                uint32_t bb[4];
                ldsm_x4_t(bb, Vb + v_off + (uint32_t)(sk * 16 * KROWH * 2 + j2 * 32));
                mma_f16(oacc[2 * j2],     a0, a1, a2, a3, bb[0], bb[1]);
                mma_f16(oacc[2 * j2 + 1], a0, a1, a2, a3, bb[2], bb[3]);
            }
        }
        __syncthreads();
    }

    float inv1 = 1.0f / l1, inv2 = 1.0f / l2;
    __half* y1 = g_y + ((size_t)b * T_ + qrow1) * D_ + h * HD_;
    __half* y2 = g_y + ((size_t)b * T_ + qrow2) * D_ + h * HD_;
#pragma unroll
    for (int n = 0; n < 16; n++) {
        int col = 8 * n + 2 * cc;
        *(__half2*)(y1 + col) = __floats2half2_rn(oacc[n][0] * inv1, oacc[n][1] * inv1);
        *(__half2*)(y2 + col) = __floats2half2_rn(oacc[n][2] * inv2, oacc[n][3] * inv2);
    }
}

// ============================================================================
extern "C" void kernel_launch(void* const* d_in, const int* in_sizes, int n_in,
                              void* d_out, int out_size)
{
    const float* x     = (const float*)d_in[0];
    const float* w_qkv = (const float*)d_in[1];
    const float* w_out = (const float*)d_in[2];
    float* out = (float*)d_out;

    cudaFuncSetAttribute(attn_kernel, cudaFuncAttributeMaxDynamicSharedMemorySize,
                         ATTN_SMEM_BYTES);
    cudaFuncSetAttribute(gemm_qkv_kernel, cudaFuncAttributeMaxDynamicSharedMemorySize,
                         GEMM_SMEM_BYTES);
    cudaFuncSetAttribute(gemm_out_kernel, cudaFuncAttributeMaxDynamicSharedMemorySize,
                         GEMM_SMEM_BYTES);

    rope_tab_kernel<<<(T_ * 64 + 255) / 256, 256>>>();
    conv_x_kernel<<<((B_ * T_ * D_ / 4) + 255) / 256, 256>>>((const float4*)x);
    conv_wq_kernel<<<((D_ * 3 * HD_ * H_ / 4) + 255) / 256, 256>>>((const float4*)w_qkv);
    conv_wo_kernel<<<((D_ * D_ / 4) + 255) / 256, 256>>>((const float4*)w_out);

    dim3 g1(6144 / 128, (B_ * T_) / 128);
    gemm_qkv_kernel<<<g1, 256, GEMM_SMEM_BYTES>>>();

    dim3 g2(T_ / 128, H_, B_);
    attn_kernel<<<g2, 256, ATTN_SMEM_BYTES>>>();

    dim3 g3(D_ / 128, (B_ * T_) / 128);
    gemm_out_kernel<<<g3, 256, GEMM_SMEM_BYTES>>>(out);
}

// round 13
// speedup vs baseline: 2.7834x; 1.0241x over previous
#include <cuda_runtime.h>
#include <cuda_fp16.h>
#include <math.h>
#include <stdint.h>

// Problem constants
#define B_  2
#define T_  2048
#define D_  2048
#define H_  16
#define HD_ 128

// ---------------- scratch (static device globals; no allocation) -------------
__device__ __align__(16) __half g_q[(size_t)B_ * H_ * T_ * HD_];   // rope applied
__device__ __align__(16) __half g_k[(size_t)B_ * H_ * T_ * HD_];
__device__ __align__(16) __half g_v[(size_t)B_ * H_ * T_ * HD_];
__device__ __align__(16) __half g_y[(size_t)B_ * T_ * D_];         // attn output
__device__ __align__(16) __half g_xh[(size_t)B_ * T_ * D_];        // x fp16
__device__ __align__(16) __half g_wqh[(size_t)D_ * 3 * HD_ * H_];  // w_qkv fp16
__device__ __align__(16) __half g_woh[(size_t)D_ * D_];            // w_out fp16
__device__ float2 g_rope_tab[T_ * 64];                             // (cos, sin)

// ============================================================================
// helpers
// ============================================================================
__device__ __forceinline__ uint32_t h2_u32(__half2 h) {
    return *reinterpret_cast<uint32_t*>(&h);
}

__device__ __forceinline__ void mma_f16(float c[4],
                                        uint32_t a0, uint32_t a1, uint32_t a2, uint32_t a3,
                                        uint32_t b0, uint32_t b1) {
    asm volatile(
        "mma.sync.aligned.m16n8k16.row.col.f32.f16.f16.f32 "
        "{%0,%1,%2,%3}, {%4,%5,%6,%7}, {%8,%9}, {%0,%1,%2,%3};"
        : "+f"(c[0]), "+f"(c[1]), "+f"(c[2]), "+f"(c[3])
        : "r"(a0), "r"(a1), "r"(a2), "r"(a3), "r"(b0), "r"(b1));
}

__device__ __forceinline__ void ldsm_x4(uint32_t r[4], uint32_t addr) {
    asm volatile("ldmatrix.sync.aligned.m8n8.x4.shared.b16 {%0,%1,%2,%3}, [%4];"
                 : "=r"(r[0]), "=r"(r[1]), "=r"(r[2]), "=r"(r[3]) : "r"(addr));
}
__device__ __forceinline__ void ldsm_x4_t(uint32_t r[4], uint32_t addr) {
    asm volatile("ldmatrix.sync.aligned.m8n8.x4.trans.shared.b16 {%0,%1,%2,%3}, [%4];"
                 : "=r"(r[0]), "=r"(r[1]), "=r"(r[2]), "=r"(r[3]) : "r"(addr));
}

__device__ __forceinline__ void cpa16s(uint32_t saddr, const void* src) {
    asm volatile("cp.async.cg.shared.global [%0], [%1], 16;" :: "r"(saddr), "l"(src));
}
__device__ __forceinline__ void cpa_commit() { asm volatile("cp.async.commit_group;"); }
template<int N> __device__ __forceinline__ void cpa_wait() {
    asm volatile("cp.async.wait_group %0;" :: "n"(N));
}

__device__ __forceinline__ uint32_t smem_u32(const void* p) {
    uint32_t a;
    asm("{ .reg .u64 t; cvta.to.shared.u64 t, %1; cvt.u32.u64 %0, t; }" : "=r"(a) : "l"(p));
    return a;
}

// ============================================================================
// prep kernels (device globals referenced ONLY from device code)
// ============================================================================
__global__ void rope_tab_kernel()
{
    int idx = blockIdx.x * blockDim.x + threadIdx.x;
    if (idx >= T_ * 64) return;
    int t = idx >> 6, i = idx & 63;
    float inv = powf(10000.0f, -((float)(2 * i)) * (1.0f / 128.0f));
    float ang = (float)t * inv;
    float s, c;
    sincosf(ang, &s, &c);
    g_rope_tab[idx] = make_float2(c, s);
}

__device__ __forceinline__ uint2 f4_to_h4(float4 v) {
    return make_uint2(h2_u32(__floats2half2_rn(v.x, v.y)),
                      h2_u32(__floats2half2_rn(v.z, v.w)));
}

__global__ void conv_x_kernel(const float4* __restrict__ in)
{
    int i = blockIdx.x * blockDim.x + threadIdx.x;
    if (i >= B_ * T_ * D_ / 4) return;
    ((uint2*)g_xh)[i] = f4_to_h4(in[i]);
}
__global__ void conv_wq_kernel(const float4* __restrict__ in)
{
    int i = blockIdx.x * blockDim.x + threadIdx.x;
    if (i >= D_ * 3 * HD_ * H_ / 4) return;
    ((uint2*)g_wqh)[i] = f4_to_h4(in[i]);
}
__global__ void conv_wo_kernel(const float4* __restrict__ in)
{
    int i = blockIdx.x * blockDim.x + threadIdx.x;
    if (i >= D_ * D_ / 4) return;
    ((uint2*)g_woh)[i] = f4_to_h4(in[i]);
}

// ============================================================================
// fp16 GEMM 128x128, k-chunk 64, 256 threads (8 warps 2m x 4n), occ 2.
// 3-stage cp.async pipeline, one __syncthreads per k-chunk (32 total).
// A smem [128][72] halves; B smem [64][136] halves per stage.
// ============================================================================
#define AROW 72
#define BROW 136
#define ABUF_BYTES (128 * AROW * 2)                 // 18432
#define BBUF_BYTES (64 * BROW * 2)                  // 17408
#define STAGE_BYTES (ABUF_BYTES + BBUF_BYTES)       // 35840
#define GEMM_SMEM_BYTES (3 * STAGE_BYTES)           // 107520

struct GemmCtx { int m0, n0, lane, warp_m, warp_n; };

template <typename Epi>
__device__ __forceinline__ void gemm_f16_cpa(const __half* __restrict__ A,
                                             const __half* __restrict__ Bg,
                                             int Kd, int Nd, Epi epi)
{
    extern __shared__ __half smg[];
    const uint32_t sb = smem_u32(smg);

    const int tid = threadIdx.x;
    const int lane = tid & 31;
    const int warp = tid >> 5;
    const int warp_m = warp & 1;
    const int warp_n = warp >> 1;
    const int m0 = blockIdx.y * 128;
    const int n0 = blockIdx.x * 128;

    float acc[4][4][4];
#pragma unroll
    for (int mt = 0; mt < 4; mt++)
#pragma unroll
        for (int nt = 0; nt < 4; nt++)
#pragma unroll
            for (int e = 0; e < 4; e++) acc[mt][nt][e] = 0.f;

    const uint32_t a_off =
        (uint32_t)((warp_m * 64 + (lane & 7) + ((lane >> 3) & 1) * 8) * AROW +
                   (lane >> 4) * 8) * 2;
    const uint32_t b_off = (uint32_t)ABUF_BYTES +
        (uint32_t)(((lane & 7) + ((lane >> 3) & 1) * 8) * BROW +
                   warp_n * 32 + (lane >> 4) * 8) * 2;

#define LOADG(it, stage)                                                          \
    {                                                                             \
        uint32_t ab = sb + (stage) * STAGE_BYTES;                                 \
        uint32_t bb = ab + ABUF_BYTES;                                            \
        int kk = (it) * 64;                                                       \
        _Pragma("unroll")                                                         \
        for (int i = 0; i < 4; i++) {                                             \
            int idx = tid + 256 * i;                                              \
            int row = idx >> 3, c = idx & 7;                                      \
            cpa16s(ab + (uint32_t)(row * (AROW * 2) + c * 16),                    \
                   A + (size_t)(m0 + row) * Kd + kk + c * 8);                     \
        }                                                                         \
        _Pragma("unroll")                                                         \
        for (int i = 0; i < 4; i++) {                                             \
            int idx = tid + 256 * i;                                              \
            int row = idx >> 4, c = idx & 15;                                     \
            cpa16s(bb + (uint32_t)(row * (BROW * 2) + c * 16),                    \
                   Bg + (size_t)(kk + row) * Nd + n0 + c * 8);                    \
        }                                                                         \
        cpa_commit();                                                             \
    }

    const int nt = Kd / 64;   // 32
    LOADG(0, 0);
    LOADG(1, 1);

    for (int it = 0; it < nt; it++) {
        if (it + 1 < nt) cpa_wait<1>(); else cpa_wait<0>();
        __syncthreads();   // stage(it%3) visible; compute of stage((it+2)%3) done in it-1

        if (it + 2 < nt) LOADG(it + 2, (it + 2) % 3);

        const uint32_t base = sb + (it % 3) * STAGE_BYTES;
#pragma unroll
        for (int s = 0; s < 4; s++) {
            uint32_t af[4][4];
#pragma unroll
            for (int mt = 0; mt < 4; mt++)
                ldsm_x4(af[mt], base + a_off + (uint32_t)(mt * 16 * AROW * 2 + s * 32));
            uint32_t bf[2][4];
#pragma unroll
            for (int nt2 = 0; nt2 < 2; nt2++)
                ldsm_x4_t(bf[nt2], base + b_off + (uint32_t)(s * 16 * BROW * 2 + nt2 * 32));
#pragma unroll
            for (int mt = 0; mt < 4; mt++)
#pragma unroll
                for (int ntv = 0; ntv < 4; ntv++)
                    mma_f16(acc[mt][ntv],
                            af[mt][0], af[mt][1], af[mt][2], af[mt][3],
                            bf[ntv >> 1][(ntv & 1) * 2], bf[ntv >> 1][(ntv & 1) * 2 + 1]);
        }
    }
#undef LOADG

    GemmCtx ctx{m0, n0, lane, warp_m, warp_n};
    epi(ctx, acc);
}

// ---------------- epilogues --------------------------------------------------
__device__ __forceinline__ void qkv_scatter_pair(int row, int col, float v0, float v1)
{
    int b = row >> 11, t = row & (T_ - 1);
    int h = col / (3 * HD_);
    int r = col % (3 * HD_);                 // always even
    size_t base = (((size_t)(b * H_ + h)) * T_ + t) * HD_;
    if (r < 2 * HD_) {
        __half* dst = (r < HD_) ? g_q : g_k;
        int rr = r & (HD_ - 1);
        float2 cs = g_rope_tab[(t << 6) + (rr >> 1)];
        float o0 = v0 * cs.x - v1 * cs.y;
        float o1 = v0 * cs.y + v1 * cs.x;
        *(__half2*)&dst[base + rr] = __floats2half2_rn(o0, o1);
    } else {
        *(__half2*)&g_v[base + r - 2 * HD_] = __floats2half2_rn(v0, v1);
    }
}

struct QkvEpi {
    __device__ __forceinline__ void operator()(const GemmCtx& c, float acc[4][4][4]) const {
#pragma unroll
        for (int mt = 0; mt < 4; mt++) {
            int row = c.m0 + c.warp_m * 64 + mt * 16 + (c.lane >> 2);
#pragma unroll
            for (int nt = 0; nt < 4; nt++) {
                int col = c.n0 + c.warp_n * 32 + nt * 8 + (c.lane & 3) * 2;
                qkv_scatter_pair(row,     col, acc[mt][nt][0], acc[mt][nt][1]);
                qkv_scatter_pair(row + 8, col, acc[mt][nt][2], acc[mt][nt][3]);
            }
        }
    }
};

struct OutEpi {
    float* C;
    __device__ __forceinline__ void operator()(const GemmCtx& c, float acc[4][4][4]) const {
#pragma unroll
        for (int mt = 0; mt < 4; mt++) {
            int row = c.m0 + c.warp_m * 64 + mt * 16 + (c.lane >> 2);
#pragma unroll
            for (int nt = 0; nt < 4; nt++) {
                int col = c.n0 + c.warp_n * 32 + nt * 8 + (c.lane & 3) * 2;
                *(float2*)(C + (size_t)row * D_ + col) =
                    make_float2(acc[mt][nt][0], acc[mt][nt][1]);
                *(float2*)(C + (size_t)(row + 8) * D_ + col) =
                    make_float2(acc[mt][nt][2], acc[mt][nt][3]);
            }
        }
    }
};

__global__ __launch_bounds__(256, 2) void gemm_qkv_kernel()
{
    gemm_f16_cpa(g_xh, g_wqh, D_, 3 * HD_ * H_, QkvEpi{});
}

__global__ __launch_bounds__(256, 2) void gemm_out_kernel(float* __restrict__ C)
{
    gemm_f16_cpa(g_y, g_woh, D_, D_, OutEpi{C});
}

// ============================================================================
// Flash attention, fp16 mma.m16n8k16 (round-12 body: reversed tile order).
// ============================================================================
#define KROWH 136
#define KV_TILE_BYTES (64 * KROWH * 2)          // 17408
#define ATTN_SMEM_BYTES (4 * KV_TILE_BYTES)     // 69632

__device__ __forceinline__ void load_kv(uint32_t sm_u, int buf,
                                        const __half* Kh, const __half* Vh,
                                        int k0, int tid)
{
    uint32_t kb = sm_u + buf * KV_TILE_BYTES;
    uint32_t vb = sm_u + 2 * KV_TILE_BYTES + buf * KV_TILE_BYTES;
#pragma unroll
    for (int i = 0; i < 4; i++) {
        int idx = tid + i * 256;
        int row = idx >> 4, c16 = idx & 15;
        cpa16s(kb + row * (KROWH * 2) + c16 * 16,
               Kh + (size_t)(k0 + row) * HD_ + c16 * 8);
    }
#pragma unroll
    for (int i = 0; i < 4; i++) {
        int idx = tid + i * 256;
        int row = idx >> 4, c16 = idx & 15;
        cpa16s(vb + row * (KROWH * 2) + c16 * 16,
               Vh + (size_t)(k0 + row) * HD_ + c16 * 8);
    }
    cpa_commit();
}

__global__ __launch_bounds__(256, 1) void attn_kernel()
{
    extern __shared__ __half smh[];
    const uint32_t sm_u = smem_u32(smh);

    const int b = blockIdx.z, h = blockIdx.y;
    const int q0 = ((int)gridDim.x - 1 - (int)blockIdx.x) * 128;  // longest first
    const __half* Qh = g_q + (((size_t)(b * H_ + h)) * T_) * HD_;
    const __half* Kh = g_k + (((size_t)(b * H_ + h)) * T_) * HD_;
    const __half* Vh = g_v + (((size_t)(b * H_ + h)) * T_) * HD_;

    const int tid = threadIdx.x;
    const int lane = tid & 31;
    const int w = tid >> 5;
    const int r1 = lane >> 2;
    const int cc = lane & 3;
    const int qrow1 = q0 + w * 16 + r1;
    const int qrow2 = qrow1 + 8;
    const int ntile = (q0 >> 6) + 2;

    load_kv(sm_u, 0, Kh, Vh, 0, tid);

    uint32_t qf[8][4];
#pragma unroll
    for (int s = 0; s < 8; s++) {
        qf[s][0] = *(const uint32_t*)(Qh + (size_t)qrow1 * HD_ + 16 * s + 2 * cc);
        qf[s][1] = *(const uint32_t*)(Qh + (size_t)qrow2 * HD_ + 16 * s + 2 * cc);
        qf[s][2] = *(const uint32_t*)(Qh + (size_t)qrow1 * HD_ + 16 * s + 8 + 2 * cc);
        qf[s][3] = *(const uint32_t*)(Qh + (size_t)qrow2 * HD_ + 16 * s + 8 + 2 * cc);
    }

    float oacc[16][4];
#pragma unroll
    for (int n = 0; n < 16; n++)
#pragma unroll
        for (int e = 0; e < 4; e++) oacc[n][e] = 0.f;
    float m1 = -1e30f, m2 = -1e30f, l1 = 0.f, l2 = 0.f;
    const float sm_scale = 0.08838834764831845f;

    const uint32_t k_off =
        (uint32_t)(((lane & 7) + (lane >> 4) * 8) * KROWH + ((lane >> 3) & 1) * 8) * 2;
    const uint32_t v_off =
        (uint32_t)(((lane & 7) + ((lane >> 3) & 1) * 8) * KROWH + (lane >> 4) * 8) * 2;

    for (int t = 0; t < ntile; t++) {
        const int k0 = t * 64;
        const uint32_t Kb = sm_u + (t & 1) * KV_TILE_BYTES;
        const uint32_t Vb = sm_u + 2 * KV_TILE_BYTES + (t & 1) * KV_TILE_BYTES;

        if (t + 1 < ntile) {
            load_kv(sm_u, (t + 1) & 1, Kh, Vh, k0 + 64, tid);
            cpa_wait<1>();
        } else {
            cpa_wait<0>();
        }
        __syncthreads();

        float sacc[8][4];
#pragma unroll
        for (int n = 0; n < 8; n++)
#pragma unroll
            for (int e = 0; e < 4; e++) sacc[n][e] = 0.f;

#pragma unroll
        for (int s = 0; s < 8; s++) {
#pragma unroll
            for (int j = 0; j < 4; j++) {
                uint32_t bb[4];
                ldsm_x4(bb, Kb + k_off + (uint32_t)(j * 16 * KROWH * 2 + s * 32));
                mma_f16(sacc[2 * j],     qf[s][0], qf[s][1], qf[s][2], qf[s][3], bb[0], bb[1]);
                mma_f16(sacc[2 * j + 1], qf[s][0], qf[s][1], qf[s][2], qf[s][3], bb[2], bb[3]);
            }
        }

        const bool need_mask = (t >= ntile - 2);
        float mx1 = -1e30f, mx2 = -1e30f;
#pragma unroll
        for (int n = 0; n < 8; n++) {
            int col = k0 + 8 * n + 2 * cc;
            float s0 = sacc[n][0] * sm_scale;
            float s1 = sacc[n][1] * sm_scale;
            float s2 = sacc[n][2] * sm_scale;
            float s3 = sacc[n][3] * sm_scale;
            if (need_mask) {
                if (col     > qrow1) s0 = -1e30f;
                if (col + 1 > qrow1) s1 = -1e30f;
                if (col     > qrow2) s2 = -1e30f;
                if (col + 1 > qrow2) s3 = -1e30f;
            }
            sacc[n][0] = s0; sacc[n][1] = s1; sacc[n][2] = s2; sacc[n][3] = s3;
            mx1 = fmaxf(mx1, fmaxf(s0, s1));
            mx2 = fmaxf(mx2, fmaxf(s2, s3));
        }
        mx1 = fmaxf(mx1, __shfl_xor_sync(0xffffffffu, mx1, 1));
        mx1 = fmaxf(mx1, __shfl_xor_sync(0xffffffffu, mx1, 2));
        mx2 = fmaxf(mx2, __shfl_xor_sync(0xffffffffu, mx2, 1));
        mx2 = fmaxf(mx2, __shfl_xor_sync(0xffffffffu, mx2, 2));
        float mn1 = fmaxf(m1, mx1), mn2 = fmaxf(m2, mx2);

        float sum1 = 0.f, sum2 = 0.f;
        uint32_t plo[8], phi[8];
#pragma unroll
        for (int n = 0; n < 8; n++) {
            float p0 = __expf(sacc[n][0] - mn1);
            float p1 = __expf(sacc[n][1] - mn1);
            float p2 = __expf(sacc[n][2] - mn2);
            float p3 = __expf(sacc[n][3] - mn2);
            __half2 hl = __floats2half2_rn(p0, p1);
            __half2 hh = __floats2half2_rn(p2, p3);
            plo[n] = h2_u32(hl);
            phi[n] = h2_u32(hh);
            float2 fl = __half22float2(hl);
            float2 fh = __half22float2(hh);
            sum1 += fl.x + fl.y;
            sum2 += fh.x + fh.y;
        }
        sum1 += __shfl_xor_sync(0xffffffffu, sum1, 1);
        sum1 += __shfl_xor_sync(0xffffffffu, sum1, 2);
        sum2 += __shfl_xor_sync(0xffffffffu, sum2, 1);
        sum2 += __shfl_xor_sync(0xffffffffu, sum2, 2);

        float sc1 = __expf(m1 - mn1), sc2 = __expf(m2 - mn2);
        l1 = l1 * sc1 + sum1;
        l2 = l2 * sc2 + sum2;
        m1 = mn1; m2 = mn2;
#pragma unroll
        for (int n = 0; n < 16; n++) {
            oacc[n][0] *= sc1; oacc[n][1] *= sc1;
            oacc[n][2] *= sc2; oacc[n][3] *= sc2;
        }

#pragma unroll
        for (int sk = 0; sk < 4; sk++) {
            uint32_t a0 = plo[2 * sk], a1 = phi[2 * sk];
            uint32_t a2 = plo[2 * sk + 1], a3 = phi[2 * sk + 1];
#pragma unroll
            for (int j2 = 0; j2 < 8; j2++) {
                uint32_t bb[4];
                ldsm_x4_t(bb, Vb + v_off + (uint32_t)(sk * 16 * KROWH * 2 + j2 * 32));
                mma_f16(oacc[2 * j2],     a0, a1, a2, a3, bb[0], bb[1]);
                mma_f16(oacc[2 * j2 + 1], a0, a1, a2, a3, bb[2], bb[3]);
            }
        }
        __syncthreads();
    }

    float inv1 = 1.0f / l1, inv2 = 1.0f / l2;
    __half* y1 = g_y + ((size_t)b * T_ + qrow1) * D_ + h * HD_;
    __half* y2 = g_y + ((size_t)b * T_ + qrow2) * D_ + h * HD_;
#pragma unroll
    for (int n = 0; n < 16; n++) {
        int col = 8 * n + 2 * cc;
        *(__half2*)(y1 + col) = __floats2half2_rn(oacc[n][0] * inv1, oacc[n][1] * inv1);
        *(__half2*)(y2 + col) = __floats2half2_rn(oacc[n][2] * inv2, oacc[n][3] * inv2);
    }
}

// ============================================================================
extern "C" void kernel_launch(void* const* d_in, const int* in_sizes, int n_in,
                              void* d_out, int out_size)
{
    const float* x     = (const float*)d_in[0];
    const float* w_qkv = (const float*)d_in[1];
    const float* w_out = (const float*)d_in[2];
    float* out = (float*)d_out;

    cudaFuncSetAttribute(attn_kernel, cudaFuncAttributeMaxDynamicSharedMemorySize,
                         ATTN_SMEM_BYTES);
    cudaFuncSetAttribute(gemm_qkv_kernel, cudaFuncAttributeMaxDynamicSharedMemorySize,
                         GEMM_SMEM_BYTES);
    cudaFuncSetAttribute(gemm_out_kernel, cudaFuncAttributeMaxDynamicSharedMemorySize,
                         GEMM_SMEM_BYTES);

    rope_tab_kernel<<<(T_ * 64 + 255) / 256, 256>>>();
    conv_x_kernel<<<((B_ * T_ * D_ / 4) + 255) / 256, 256>>>((const float4*)x);
    conv_wq_kernel<<<((D_ * 3 * HD_ * H_ / 4) + 255) / 256, 256>>>((const float4*)w_qkv);
    conv_wo_kernel<<<((D_ * D_ / 4) + 255) / 256, 256>>>((const float4*)w_out);

    dim3 g1(6144 / 128, (B_ * T_) / 128);
    gemm_qkv_kernel<<<g1, 256, GEMM_SMEM_BYTES>>>();

    dim3 g2(T_ / 128, H_, B_);
    attn_kernel<<<g2, 256, ATTN_SMEM_BYTES>>>();

    dim3 g3(D_ / 128, (B_ * T_) / 128);
    gemm_out_kernel<<<g3, 256, GEMM_SMEM_BYTES>>>(out);
}